// round 3
// baseline (speedup 1.0000x reference)
#include <cuda_runtime.h>
#include <cuda_bf16.h>
#include <cstdint>

// Problem constants
#define Bsz 64
#define Tt  512
#define Ee  512
#define Hh  512
#define G4  2048          // 4*H
#define NC  64            // CTAs per direction in recurrence
#define CH  8             // hidden units per CTA (H / NC)
#define HS2 520           // padded SMEM row stride for h (floats, even, 8B-aligned rows)
#define REC_THREADS 512
#define REC_SMEM ((512*32 + 64*HS2)*4)

// ---------------- scratch (static device memory; no allocation) ----------------
__device__ float g_x  [(size_t)Bsz*Tt*Ee];
__device__ float g_xz0[(size_t)Bsz*Tt*G4];
__device__ float g_xz1[(size_t)Bsz*Tt*G4];
__device__ float g_l1 [(size_t)Bsz*Tt*2*Hh];
__device__ float g_hbuf[2*2*Bsz*Hh];              // [dir][parity][B][H]
__device__ int   g_cnt[4];                        // per (layer,dir) barrier counters

// ---------------- f32x2 packed-FMA helpers (B300 FFMA2) ----------------
__device__ __forceinline__ void fma2(unsigned long long &d, unsigned long long a,
                                     unsigned long long b) {
    asm("fma.rn.f32x2 %0, %1, %2, %0;" : "+l"(d) : "l"(a), "l"(b));
}
__device__ __forceinline__ unsigned long long pack2(float lo, float hi) {
    unsigned long long r;
    asm("mov.b64 %0, {%1, %2};" : "=l"(r) : "f"(lo), "f"(hi));
    return r;
}
__device__ __forceinline__ unsigned long long dup2(float x) { return pack2(x, x); }
__device__ __forceinline__ float2 unpack2(unsigned long long v) {
    float2 r;
    asm("mov.b64 {%0, %1}, %2;" : "=f"(r.x), "=f"(r.y) : "l"(v));
    return r;
}
__device__ __forceinline__ float sigm(float x) { return 1.0f / (1.0f + expf(-x)); }

// ---------------- init ----------------
__global__ void k_init(int full) {
    int i = blockIdx.x * blockDim.x + threadIdx.x;
    float4 z = make_float4(0.f, 0.f, 0.f, 0.f);
    if (i < 2*2*Bsz*Hh/4) ((float4*)g_hbuf)[i] = z;
    if (full && i < 4) g_cnt[i] = 0;
}

// ---------------- embedding gather ----------------
__global__ void k_gather(const int* __restrict__ ids, const float* __restrict__ emb) {
    int i = blockIdx.x * blockDim.x + threadIdx.x;
    int bt = i >> 7;
    int c  = i & 127;
    int id = __ldg(&ids[bt]);
    ((float4*)g_x)[i] = __ldg((const float4*)emb + (size_t)id * 128 + c);
}

// ---------------- SGEMM (fp32, FFMA2): Y[M,2048] = X[M,K] @ W[K,2048] + bias ----------------
__global__ void __launch_bounds__(128)
k_sgemm(const float* __restrict__ X, const float* __restrict__ W,
        const float* __restrict__ bias, float* __restrict__ Y, int K) {
    const int N = 2048;
    __shared__ float As[16][64];
    __shared__ float Bs[16][64];

    const int tid = threadIdx.x;
    const int bm = blockIdx.y * 64;
    const int bn = blockIdx.x * 64;

    const int a_m = tid >> 2;
    const int a_k = (tid & 3) * 4;
    const int b_k = tid >> 4;
    const int b_n = (tid & 15) * 4;
    const int mt  = (tid & 15) * 4;
    const int nt  = (tid >> 4) * 8;

    unsigned long long acc[4][4];
#pragma unroll
    for (int i = 0; i < 4; i++)
#pragma unroll
        for (int j = 0; j < 4; j++) acc[i][j] = 0ULL;

    for (int k0 = 0; k0 < K; k0 += 16) {
        float4 av0 = *(const float4*)&X[(size_t)(bm + a_m)      * K + k0 + a_k];
        float4 av1 = *(const float4*)&X[(size_t)(bm + a_m + 32) * K + k0 + a_k];
        float4 bv0 = *(const float4*)&W[(size_t)(k0 + b_k)     * N + bn + b_n];
        float4 bv1 = *(const float4*)&W[(size_t)(k0 + b_k + 8) * N + bn + b_n];
        __syncthreads();
        As[a_k+0][a_m] = av0.x; As[a_k+1][a_m] = av0.y;
        As[a_k+2][a_m] = av0.z; As[a_k+3][a_m] = av0.w;
        As[a_k+0][a_m+32] = av1.x; As[a_k+1][a_m+32] = av1.y;
        As[a_k+2][a_m+32] = av1.z; As[a_k+3][a_m+32] = av1.w;
        *(float4*)&Bs[b_k][b_n]     = bv0;
        *(float4*)&Bs[b_k + 8][b_n] = bv1;
        __syncthreads();
#pragma unroll
        for (int k = 0; k < 16; k++) {
            float4 a = *(const float4*)&As[k][mt];
            ulonglong2 u0 = *(const ulonglong2*)&Bs[k][nt];
            ulonglong2 u1 = *(const ulonglong2*)&Bs[k][nt + 4];
            unsigned long long d0 = dup2(a.x), d1 = dup2(a.y),
                               d2 = dup2(a.z), d3 = dup2(a.w);
            fma2(acc[0][0], d0, u0.x); fma2(acc[0][1], d0, u0.y);
            fma2(acc[0][2], d0, u1.x); fma2(acc[0][3], d0, u1.y);
            fma2(acc[1][0], d1, u0.x); fma2(acc[1][1], d1, u0.y);
            fma2(acc[1][2], d1, u1.x); fma2(acc[1][3], d1, u1.y);
            fma2(acc[2][0], d2, u0.x); fma2(acc[2][1], d2, u0.y);
            fma2(acc[2][2], d2, u1.x); fma2(acc[2][3], d2, u1.y);
            fma2(acc[3][0], d3, u0.x); fma2(acc[3][1], d3, u0.y);
            fma2(acc[3][2], d3, u1.x); fma2(acc[3][3], d3, u1.y);
        }
    }
#pragma unroll
    for (int i = 0; i < 4; i++) {
        int row = bm + mt + i;
        float* yr = Y + (size_t)row * N + bn + nt;
#pragma unroll
        for (int j = 0; j < 4; j++) {
            float2 v = unpack2(acc[i][j]);
            int c = bn + nt + j * 2;
            yr[j*2]     = v.x + bias[c];
            yr[j*2 + 1] = v.y + bias[c + 1];
        }
    }
}

// ---------------- persistent bidirectional LSTM recurrence ----------------
// 128 CTAs: dir = blockIdx/64, hidden chunk = blockIdx%64. 512 threads:
// thread = (batch row b = tid>>3, local hidden unit jj = tid&7).
// FFMA2 lanes = (k even, k odd) partial sums -> h operand is a natural LDS.64
// pair (no dup MOVs); U repacked in SMEM as [kpair][jj][gate][2] so 2 LDS.128
// feed all 4 gate FFMA2s. Horizontal add once per step in the epilogue.
__global__ void __launch_bounds__(REC_THREADS, 1)
k_rec(const float* __restrict__ xzf, const float* __restrict__ xzb,
      const float* __restrict__ Uf,  const float* __restrict__ Ub,
      float* __restrict__ hs_out, float* st_out, int layer) {
    extern __shared__ float sm[];
    float* Us = sm;               // [256 kpairs][8 jj][4 gates][2] = 16384 floats
    float* Hs = sm + 512 * 32;    // [64][HS2]

    const int dir = blockIdx.x >> 6;
    const int cid = blockIdx.x & 63;
    const float* xz = dir ? xzb : xzf;
    const float* U  = dir ? Ub  : Uf;
    int* cnt = &g_cnt[layer * 2 + dir];
    const int jbase = cid * CH;
    const int tid = threadIdx.x;

    // pack U slice: Us[m*64 + jj*8 + g*2 + e] = U[(2m+e)][g*512 + jbase + jj]
    for (int idx = tid; idx < 512 * 32; idx += REC_THREADS) {
        int m = idx >> 6, r = idx & 63;
        int jq = r >> 3, q = r & 7, g = q >> 1, e = q & 1;
        Us[idx] = U[(size_t)(2 * m + e) * G4 + g * Hh + jbase + jq];
    }

    const int b  = tid >> 3;          // batch row 0..63
    const int jj = tid & 7;           // local hidden unit
    const int jg = jbase + jj;
    float cst = 0.f;

    // staging map: 8 threads per batch row, 64 contiguous floats each
    const int sb = tid >> 3;
    const int sko = (tid & 7) * 64;

    float* HB0 = g_hbuf + (size_t)dir * 2 * Bsz * Hh;
    float* HB1 = HB0 + Bsz * Hh;
    const float* uj = Us + jj * 8;
    const float* hrow = Hs + b * HS2;
    __syncthreads();

    for (int s = 0; s < Tt; ++s) {
        const int tt = dir ? (Tt - 1 - s) : s;
        const float* hp = (s & 1) ? HB1 : HB0;
        float*       hn = (s & 1) ? HB0 : HB1;

        // xz gate pre-activations first (DRAM latency overlaps the h staging)
        const float* xzp = xz + (size_t)tt * G4 + jg;
        const size_t ob = (size_t)b * Tt * G4;
        float xi = __ldcs(xzp + ob);
        float xf = __ldcs(xzp + ob + 512);
        float xg = __ldcs(xzp + ob + 1024);
        float xo = __ldcs(xzp + ob + 1536);

        // stage h_prev (L2 -> SMEM): 16 float4/thread in 2 batched rounds
        {
            const float4* src = (const float4*)(hp + sb * 512 + sko);
            float4*       dst = (float4*)(Hs + sb * HS2 + sko);
#pragma unroll
            for (int r = 0; r < 2; ++r) {
                float4 t[8];
#pragma unroll
                for (int u = 0; u < 8; ++u) t[u] = __ldcg(src + r * 8 + u);
#pragma unroll
                for (int u = 0; u < 8; ++u) dst[r * 8 + u] = t[u];
            }
        }
        __syncthreads();

        unsigned long long aI = 0ULL, aF = 0ULL, aG = 0ULL, aO = 0ULL;
#pragma unroll 8
        for (int m = 0; m < 256; ++m) {
            unsigned long long hh = *(const unsigned long long*)&hrow[2 * m];
            ulonglong2 uif = *(const ulonglong2*)&uj[m * 64];
            ulonglong2 ugo = *(const ulonglong2*)&uj[m * 64 + 4];
            fma2(aI, hh, uif.x); fma2(aF, hh, uif.y);
            fma2(aG, hh, ugo.x); fma2(aO, hh, ugo.y);
        }

        float2 vi = unpack2(aI), vf = unpack2(aF);
        float2 vg = unpack2(aG), vo = unpack2(aO);
        float zi = vi.x + vi.y + xi;
        float zf = vf.x + vf.y + xf;
        float zg = vg.x + vg.y + xg;
        float zo = vo.x + vo.y + xo;
        float ig = sigm(zi), fg = sigm(zf);
        float gg = tanhf(zg), og = sigm(zo);
        cst = fg * cst + ig * gg;
        float hv = og * tanhf(cst);

        __stcg(&hn[b * Hh + jg], hv);
        __stcs(&hs_out[((size_t)b * Tt + tt) * 1024 + dir * Hh + jg], hv);
        if (st_out != nullptr && s == Tt - 1) {
            st_out[b * 1024 + dir * Hh + jg] = hv;                  // state_h
            st_out[Bsz * 1024 + b * 1024 + dir * Hh + jg] = cst;    // state_c
        }

        // per-direction step barrier (monotonic counter)
        __threadfence();
        __syncthreads();
        if (tid == 0) {
            atomicAdd(cnt, 1);
            const int target = NC * (s + 1);
            while (*(volatile int*)cnt < target) __nanosleep(32);
        }
        __syncthreads();
        __threadfence();
    }
}

// ---------------- launch sequence ----------------
extern "C" void kernel_launch(void* const* d_in, const int* in_sizes, int n_in,
                              void* d_out, int out_size) {
    const int*   ids = (const int*)d_in[0];
    const float* emb = (const float*)d_in[1];
    const float *W1f = (const float*)d_in[2],  *U1f = (const float*)d_in[3],
                *b1f = (const float*)d_in[4];
    const float *W1b = (const float*)d_in[5],  *U1b = (const float*)d_in[6],
                *b1b = (const float*)d_in[7];
    const float *W2f = (const float*)d_in[8],  *U2f = (const float*)d_in[9],
                *b2f = (const float*)d_in[10];
    const float *W2b = (const float*)d_in[11], *U2b = (const float*)d_in[12],
                *b2b = (const float*)d_in[13];
    float* out = (float*)d_out;

    float *px, *pxz0, *pxz1, *pl1;
    cudaGetSymbolAddress((void**)&px,   g_x);
    cudaGetSymbolAddress((void**)&pxz0, g_xz0);
    cudaGetSymbolAddress((void**)&pxz1, g_xz1);
    cudaGetSymbolAddress((void**)&pl1,  g_l1);

    cudaFuncSetAttribute(k_rec, cudaFuncAttributeMaxDynamicSharedMemorySize, REC_SMEM);

    k_init<<<128, 256>>>(1);
    k_gather<<<16384, 256>>>(ids, emb);

    dim3 gg(G4 / 64, (Bsz * Tt) / 64);   // (32, 512)
    k_sgemm<<<gg, 128>>>(px, W1f, b1f, pxz0, Ee);
    k_sgemm<<<gg, 128>>>(px, W1b, b1b, pxz1, Ee);
    k_rec<<<2 * NC, REC_THREADS, REC_SMEM>>>(pxz0, pxz1, U1f, U1b, pl1, nullptr, 0);
    k_init<<<128, 256>>>(0);
    k_sgemm<<<gg, 128>>>(pl1, W2f, b2f, pxz0, 2 * Hh);
    k_sgemm<<<gg, 128>>>(pl1, W2b, b2b, pxz1, 2 * Hh);
    k_rec<<<2 * NC, REC_THREADS, REC_SMEM>>>(pxz0, pxz1, U2f, U2b, out,
                                             out + (size_t)Bsz * Tt * 1024, 1);
}

// round 4
// speedup vs baseline: 1.7578x; 1.7578x over previous
#include <cuda_runtime.h>
#include <cuda_bf16.h>
#include <cstdint>

// Problem constants
#define Bsz 64
#define Tt  512
#define Ee  512
#define Hh  512
#define G4  2048          // 4*H
#define NC  64            // CTAs per direction in recurrence
#define CH  8             // hidden units per CTA (H / NC)
#define HSS 516           // padded SMEM stride for h  (516 % 32 == 4 -> conflict-free)
#define REC_THREADS 256
#define REC_SMEM ((512*32 + 64*HSS)*4)

// GEMM tile config
#define GBM 128
#define GBN 128
#define GBK 16
#define GPAD 132          // padded SMEM row stride (floats), 16B-aligned

// ---------------- scratch (static device memory; no allocation) ----------------
__device__ float g_x  [(size_t)Bsz*Tt*Ee];
__device__ float g_xz0[(size_t)Bsz*Tt*G4];
__device__ float g_xz1[(size_t)Bsz*Tt*G4];
__device__ float g_l1 [(size_t)Bsz*Tt*2*Hh];
__device__ float g_hbuf[2*2*Bsz*Hh];              // [dir][parity][B][H]
__device__ int   g_cnt[4];                        // per (layer,dir) barrier counters

// ---------------- f32x2 packed-FMA helpers (B300 FFMA2) ----------------
__device__ __forceinline__ void fma2(unsigned long long &d, unsigned long long a,
                                     unsigned long long b) {
    asm("fma.rn.f32x2 %0, %1, %2, %0;" : "+l"(d) : "l"(a), "l"(b));
}
__device__ __forceinline__ unsigned long long pack2(float lo, float hi) {
    unsigned long long r;
    asm("mov.b64 %0, {%1, %2};" : "=l"(r) : "f"(lo), "f"(hi));
    return r;
}
__device__ __forceinline__ unsigned long long dup2(float x) { return pack2(x, x); }
__device__ __forceinline__ float2 unpack2(unsigned long long v) {
    float2 r;
    asm("mov.b64 {%0, %1}, %2;" : "=f"(r.x), "=f"(r.y) : "l"(v));
    return r;
}
__device__ __forceinline__ float sigm(float x) { return 1.0f / (1.0f + expf(-x)); }

// ---------------- init ----------------
__global__ void k_init(int full) {
    int i = blockIdx.x * blockDim.x + threadIdx.x;
    float4 z = make_float4(0.f, 0.f, 0.f, 0.f);
    if (i < 2*2*Bsz*Hh/4) ((float4*)g_hbuf)[i] = z;
    if (full && i < 4) g_cnt[i] = 0;
}

// ---------------- embedding gather ----------------
__global__ void k_gather(const int* __restrict__ ids, const float* __restrict__ emb) {
    int i = blockIdx.x * blockDim.x + threadIdx.x;
    int bt = i >> 7;
    int c  = i & 127;
    int id = __ldg(&ids[bt]);
    ((float4*)g_x)[i] = __ldg((const float4*)emb + (size_t)id * 128 + c);
}

// ---------------- SGEMM (fp32, FFMA2): Y[M,2048] = X[M,K] @ W[K,2048] + bias ----------------
// 128x128 tile, BK=16, 256 threads, 8x8 thread tile, warp = 8m x 4n lanes.
__global__ void __launch_bounds__(256)
k_sgemm(const float* __restrict__ X, const float* __restrict__ W,
        const float* __restrict__ bias, float* __restrict__ Y, int K) {
    const int N = 2048;
    __shared__ float As[GBK][GPAD];   // transposed: As[k][m]
    __shared__ float Bs[GBK][GPAD];

    const int tid = threadIdx.x;
    const int bm = blockIdx.y * GBM;
    const int bn = blockIdx.x * GBN;

    // loaders
    const int a_m = tid >> 2;            // 0..63 (+64 for second row)
    const int a_k = (tid & 3) * 4;       // 0,4,8,12
    const int b_k = tid >> 4;            // 0..15
    const int b_n = (tid & 15) * 4;      // 0..60 (+64 for second col)

    // compute mapping: 8 warps = 2 m-warps x 4 n-warps; lane = 8m x 4n
    const int warp = tid >> 5;
    const int lane = tid & 31;
    const int mt = (warp & 1) * 64 + (lane & 7) * 8;
    const int nt = (warp >> 1) * 32 + (lane >> 3) * 8;

    unsigned long long acc[8][4];
#pragma unroll
    for (int i = 0; i < 8; i++)
#pragma unroll
        for (int j = 0; j < 4; j++) acc[i][j] = 0ULL;

    for (int k0 = 0; k0 < K; k0 += GBK) {
        float4 av0 = *(const float4*)&X[(size_t)(bm + a_m)      * K + k0 + a_k];
        float4 av1 = *(const float4*)&X[(size_t)(bm + a_m + 64) * K + k0 + a_k];
        float4 bv0 = *(const float4*)&W[(size_t)(k0 + b_k) * N + bn + b_n];
        float4 bv1 = *(const float4*)&W[(size_t)(k0 + b_k) * N + bn + b_n + 64];
        __syncthreads();
        As[a_k+0][a_m] = av0.x; As[a_k+1][a_m] = av0.y;
        As[a_k+2][a_m] = av0.z; As[a_k+3][a_m] = av0.w;
        As[a_k+0][a_m+64] = av1.x; As[a_k+1][a_m+64] = av1.y;
        As[a_k+2][a_m+64] = av1.z; As[a_k+3][a_m+64] = av1.w;
        *(float4*)&Bs[b_k][b_n]      = bv0;
        *(float4*)&Bs[b_k][b_n + 64] = bv1;
        __syncthreads();
#pragma unroll
        for (int k = 0; k < GBK; k++) {
            float4 a0 = *(const float4*)&As[k][mt];
            float4 a1 = *(const float4*)&As[k][mt + 4];
            ulonglong2 u0 = *(const ulonglong2*)&Bs[k][nt];
            ulonglong2 u1 = *(const ulonglong2*)&Bs[k][nt + 4];
#pragma unroll
            for (int i = 0; i < 4; i++) {
                unsigned long long d = dup2((&a0.x)[i]);
                fma2(acc[i][0], d, u0.x); fma2(acc[i][1], d, u0.y);
                fma2(acc[i][2], d, u1.x); fma2(acc[i][3], d, u1.y);
            }
#pragma unroll
            for (int i = 0; i < 4; i++) {
                unsigned long long d = dup2((&a1.x)[i]);
                fma2(acc[4+i][0], d, u0.x); fma2(acc[4+i][1], d, u0.y);
                fma2(acc[4+i][2], d, u1.x); fma2(acc[4+i][3], d, u1.y);
            }
        }
    }

    // epilogue: add bias, store
    float bs[8];
#pragma unroll
    for (int j = 0; j < 8; j++) bs[j] = bias[bn + nt + j];
#pragma unroll
    for (int i = 0; i < 8; i++) {
        float* yr = Y + (size_t)(bm + mt + i) * N + bn + nt;
        float4 v0, v1;
        float2 p0 = unpack2(acc[i][0]), p1 = unpack2(acc[i][1]);
        float2 p2 = unpack2(acc[i][2]), p3 = unpack2(acc[i][3]);
        v0.x = p0.x + bs[0]; v0.y = p0.y + bs[1];
        v0.z = p1.x + bs[2]; v0.w = p1.y + bs[3];
        v1.x = p2.x + bs[4]; v1.y = p2.y + bs[5];
        v1.z = p3.x + bs[6]; v1.w = p3.y + bs[7];
        *(float4*)yr       = v0;
        *(float4*)(yr + 4) = v1;
    }
}

// ---------------- persistent bidirectional LSTM recurrence (R1 layout + xz prefetch) ----------------
// 128 CTAs: dir = blockIdx/64, hidden chunk = blockIdx%64, 256 threads.
// U slice resident in SMEM (gate-interleaved); h broadcast via L2, staged to
// SMEM with blocking ldcg; c state in registers; per-direction counter barrier.
// xz pre-activations for step s+1 are prefetched into registers right before
// the barrier so DRAM latency hides under the barrier wait.
__global__ void __launch_bounds__(REC_THREADS, 1)
k_rec(const float* __restrict__ xzf, const float* __restrict__ xzb,
      const float* __restrict__ Uf,  const float* __restrict__ Ub,
      float* __restrict__ hs_out, float* st_out, int layer) {
    extern __shared__ float sm[];
    float* Us = sm;               // [512][32]: k*32 + jj*4 + gate
    float* Hs = sm + 512 * 32;    // [64][HSS]

    const int dir = blockIdx.x >> 6;
    const int cid = blockIdx.x & 63;
    const float* xz = dir ? xzb : xzf;
    const float* U  = dir ? Ub  : Uf;
    int* cnt = &g_cnt[layer * 2 + dir];
    const int jbase = cid * CH;
    const int tid = threadIdx.x;

    for (int idx = tid; idx < 512 * 32; idx += REC_THREADS) {
        int k = idx >> 5, cc = idx & 31;
        int jq = cc >> 2, g = cc & 3;
        Us[idx] = U[(size_t)k * G4 + g * Hh + jbase + jq];
    }

    const int bp = tid >> 3;          // batch pair 0..31
    const int jj = tid & 7;
    const int b0 = bp * 2, b1 = b0 + 1;
    const int jg = jbase + jj;
    float c0 = 0.f, c1 = 0.f;

    float* HB0 = g_hbuf + (size_t)dir * 2 * Bsz * Hh;
    float* HB1 = HB0 + Bsz * Hh;
    const float* uptr = Us + jj * 4;
    __syncthreads();

    // prefetch xz for step 0
    const size_t o0 = (size_t)b0 * Tt * G4, o1 = (size_t)b1 * Tt * G4;
    const int t0 = dir ? (Tt - 1) : 0;
    const float* xp0 = xz + (size_t)t0 * G4 + jg;
    float x00 = __ldcs(xp0 + o0),        x01 = __ldcs(xp0 + o0 + 512);
    float x02 = __ldcs(xp0 + o0 + 1024), x03 = __ldcs(xp0 + o0 + 1536);
    float x10 = __ldcs(xp0 + o1),        x11 = __ldcs(xp0 + o1 + 512);
    float x12 = __ldcs(xp0 + o1 + 1024), x13 = __ldcs(xp0 + o1 + 1536);

    for (int s = 0; s < Tt; ++s) {
        const int tt = dir ? (Tt - 1 - s) : s;
        const float* hp = (s & 1) ? HB1 : HB0;
        float*       hn = (s & 1) ? HB0 : HB1;

        // stage h_prev (L2 -> SMEM), L1-bypassed for cross-CTA coherence
        for (int idx = tid * 4; idx < Bsz * Hh; idx += REC_THREADS * 4) {
            float4 v = __ldcg((const float4*)(hp + idx));
            int b = idx >> 9, k = idx & 511;
            *(float4*)&Hs[b * HSS + k] = v;
        }
        __syncthreads();

        unsigned long long a001 = pack2(x00, x01);
        unsigned long long a023 = pack2(x02, x03);
        unsigned long long a101 = pack2(x10, x11);
        unsigned long long a123 = pack2(x12, x13);

#pragma unroll 8
        for (int k = 0; k < Hh; ++k) {
            float h0 = Hs[b0 * HSS + k];
            float h1 = Hs[b1 * HSS + k];
            ulonglong2 uu = *(const ulonglong2*)(uptr + k * 32);
            unsigned long long h00 = dup2(h0), h11 = dup2(h1);
            fma2(a001, h00, uu.x); fma2(a023, h00, uu.y);
            fma2(a101, h11, uu.x); fma2(a123, h11, uu.y);
        }

        float2 zif0 = unpack2(a001), zgo0 = unpack2(a023);
        float2 zif1 = unpack2(a101), zgo1 = unpack2(a123);
        float i0 = sigm(zif0.x), f0 = sigm(zif0.y);
        float gg0 = tanhf(zgo0.x), og0 = sigm(zgo0.y);
        c0 = f0 * c0 + i0 * gg0;
        float h0n = og0 * tanhf(c0);
        float i1 = sigm(zif1.x), f1 = sigm(zif1.y);
        float gg1 = tanhf(zgo1.x), og1 = sigm(zgo1.y);
        c1 = f1 * c1 + i1 * gg1;
        float h1n = og1 * tanhf(c1);

        hn[b0 * Hh + jg] = h0n;
        hn[b1 * Hh + jg] = h1n;
        hs_out[((size_t)b0 * Tt + tt) * 1024 + dir * Hh + jg] = h0n;
        hs_out[((size_t)b1 * Tt + tt) * 1024 + dir * Hh + jg] = h1n;
        if (st_out != nullptr && s == Tt - 1) {
            st_out[b0 * 1024 + dir * Hh + jg] = h0n;
            st_out[b1 * 1024 + dir * Hh + jg] = h1n;
            st_out[Bsz * 1024 + b0 * 1024 + dir * Hh + jg] = c0;
            st_out[Bsz * 1024 + b1 * 1024 + dir * Hh + jg] = c1;
        }

        // prefetch next step's xz (overlaps with barrier wait)
        if (s + 1 < Tt) {
            const int tn = dir ? (Tt - 2 - s) : (s + 1);
            const float* xp = xz + (size_t)tn * G4 + jg;
            x00 = __ldcs(xp + o0);        x01 = __ldcs(xp + o0 + 512);
            x02 = __ldcs(xp + o0 + 1024); x03 = __ldcs(xp + o0 + 1536);
            x10 = __ldcs(xp + o1);        x11 = __ldcs(xp + o1 + 512);
            x12 = __ldcs(xp + o1 + 1024); x13 = __ldcs(xp + o1 + 1536);
        }

        // inter-CTA step barrier (per direction)
        __threadfence();
        __syncthreads();
        if (tid == 0) {
            atomicAdd(cnt, 1);
            const int target = NC * (s + 1);
            while (*(volatile int*)cnt < target) __nanosleep(32);
        }
        __syncthreads();
        __threadfence();
    }
}

// ---------------- launch sequence ----------------
extern "C" void kernel_launch(void* const* d_in, const int* in_sizes, int n_in,
                              void* d_out, int out_size) {
    const int*   ids = (const int*)d_in[0];
    const float* emb = (const float*)d_in[1];
    const float *W1f = (const float*)d_in[2],  *U1f = (const float*)d_in[3],
                *b1f = (const float*)d_in[4];
    const float *W1b = (const float*)d_in[5],  *U1b = (const float*)d_in[6],
                *b1b = (const float*)d_in[7];
    const float *W2f = (const float*)d_in[8],  *U2f = (const float*)d_in[9],
                *b2f = (const float*)d_in[10];
    const float *W2b = (const float*)d_in[11], *U2b = (const float*)d_in[12],
                *b2b = (const float*)d_in[13];
    float* out = (float*)d_out;

    float *px, *pxz0, *pxz1, *pl1;
    cudaGetSymbolAddress((void**)&px,   g_x);
    cudaGetSymbolAddress((void**)&pxz0, g_xz0);
    cudaGetSymbolAddress((void**)&pxz1, g_xz1);
    cudaGetSymbolAddress((void**)&pl1,  g_l1);

    cudaFuncSetAttribute(k_rec, cudaFuncAttributeMaxDynamicSharedMemorySize, REC_SMEM);

    k_init<<<128, 256>>>(1);
    k_gather<<<16384, 256>>>(ids, emb);

    dim3 gg(G4 / GBN, (Bsz * Tt) / GBM);   // (16, 256)
    k_sgemm<<<gg, 256>>>(px, W1f, b1f, pxz0, Ee);
    k_sgemm<<<gg, 256>>>(px, W1b, b1b, pxz1, Ee);
    k_rec<<<2 * NC, REC_THREADS, REC_SMEM>>>(pxz0, pxz1, U1f, U1b, pl1, nullptr, 0);
    k_init<<<128, 256>>>(0);
    k_sgemm<<<gg, 256>>>(pl1, W2f, b2f, pxz0, 2 * Hh);
    k_sgemm<<<gg, 256>>>(pl1, W2b, b2b, pxz1, 2 * Hh);
    k_rec<<<2 * NC, REC_THREADS, REC_SMEM>>>(pxz0, pxz1, U2f, U2b, out,
                                             out + (size_t)Bsz * Tt * 1024, 1);
}

// round 5
// speedup vs baseline: 2.4758x; 1.4084x over previous
#include <cuda_runtime.h>
#include <cuda_bf16.h>
#include <cstdint>

// Problem constants
#define Bsz 64
#define Tt  512
#define Ee  512
#define Hh  512
#define G4  2048          // 4*H
#define NC  64            // CTAs per direction in recurrence
#define CH  8             // hidden units per CTA (H / NC)
#define HSS 516           // padded SMEM stride for h  (516 % 32 == 4 -> conflict-free)
#define REC_THREADS 256
#define REC_SMEM ((512*32 + 64*HSS)*4)

// ---------------- scratch (static device memory; no allocation) ----------------
__device__ float g_x  [(size_t)Bsz*Tt*Ee];
__device__ float g_xz0[(size_t)Bsz*Tt*G4];
__device__ float g_xz1[(size_t)Bsz*Tt*G4];
__device__ float g_l1 [(size_t)Bsz*Tt*2*Hh];
__device__ float g_hbuf[2*2*Bsz*Hh];              // [dir][parity][B][H]
__device__ int   g_cnt[4];                        // per (layer,dir) barrier counters
// bf16 split buffers for tensor-core projections
__device__ __nv_bfloat16 g_ahi [(size_t)Bsz*Tt*1024];   // A hi (max K=1024)
__device__ __nv_bfloat16 g_alo [(size_t)Bsz*Tt*1024];   // A lo
__device__ __nv_bfloat16 g_whiT[(size_t)G4*1024];       // W hi, transposed [N][K]
__device__ __nv_bfloat16 g_wloT[(size_t)G4*1024];       // W lo, transposed [N][K]

// ---------------- f32x2 packed-FMA helpers (kept for k_rec) ----------------
__device__ __forceinline__ void fma2(unsigned long long &d, unsigned long long a,
                                     unsigned long long b) {
    asm("fma.rn.f32x2 %0, %1, %2, %0;" : "+l"(d) : "l"(a), "l"(b));
}
__device__ __forceinline__ unsigned long long pack2(float lo, float hi) {
    unsigned long long r;
    asm("mov.b64 %0, {%1, %2};" : "=l"(r) : "f"(lo), "f"(hi));
    return r;
}
__device__ __forceinline__ unsigned long long dup2(float x) { return pack2(x, x); }
__device__ __forceinline__ float2 unpack2(unsigned long long v) {
    float2 r;
    asm("mov.b64 {%0, %1}, %2;" : "=f"(r.x), "=f"(r.y) : "l"(v));
    return r;
}
__device__ __forceinline__ float sigm(float x) { return 1.0f / (1.0f + expf(-x)); }

// ---------------- init ----------------
__global__ void k_init(int full) {
    int i = blockIdx.x * blockDim.x + threadIdx.x;
    float4 z = make_float4(0.f, 0.f, 0.f, 0.f);
    if (i < 2*2*Bsz*Hh/4) ((float4*)g_hbuf)[i] = z;
    if (full && i < 4) g_cnt[i] = 0;
}

// ---------------- embedding gather ----------------
__global__ void k_gather(const int* __restrict__ ids, const float* __restrict__ emb) {
    int i = blockIdx.x * blockDim.x + threadIdx.x;
    int bt = i >> 7;
    int c  = i & 127;
    int id = __ldg(&ids[bt]);
    ((float4*)g_x)[i] = __ldg((const float4*)emb + (size_t)id * 128 + c);
}

// ---------------- A split: fp32 -> bf16 hi + bf16 lo (elementwise, f4-vectorized) --------
__global__ void k_splitA(const float* __restrict__ X, __nv_bfloat16* __restrict__ hi,
                         __nv_bfloat16* __restrict__ lo, int n4) {
    int i = blockIdx.x * blockDim.x + threadIdx.x;
    if (i >= n4) return;
    float4 v = __ldcs((const float4*)X + i);
    __nv_bfloat16 h0 = __float2bfloat16(v.x), h1 = __float2bfloat16(v.y);
    __nv_bfloat16 h2 = __float2bfloat16(v.z), h3 = __float2bfloat16(v.w);
    __nv_bfloat16 l0 = __float2bfloat16(v.x - __bfloat162float(h0));
    __nv_bfloat16 l1 = __float2bfloat16(v.y - __bfloat162float(h1));
    __nv_bfloat16 l2 = __float2bfloat16(v.z - __bfloat162float(h2));
    __nv_bfloat16 l3 = __float2bfloat16(v.w - __bfloat162float(h3));
    ((__nv_bfloat162*)hi)[i*2]   = __nv_bfloat162(h0, h1);
    ((__nv_bfloat162*)hi)[i*2+1] = __nv_bfloat162(h2, h3);
    ((__nv_bfloat162*)lo)[i*2]   = __nv_bfloat162(l0, l1);
    ((__nv_bfloat162*)lo)[i*2+1] = __nv_bfloat162(l2, l3);
}

// ---------------- W split + transpose: W[K][2048] fp32 -> WhiT/WloT[2048][K] bf16 --------
__global__ void __launch_bounds__(256)
k_splitW(const float* __restrict__ W, __nv_bfloat16* __restrict__ hiT,
         __nv_bfloat16* __restrict__ loT, int K) {
    __shared__ float t[32][33];
    const int kb = blockIdx.y * 32, nb = blockIdx.x * 32;
    const int tx = threadIdx.x, ty = threadIdx.y;   // block (32, 8)
#pragma unroll
    for (int r = ty; r < 32; r += 8)
        t[r][tx] = W[(size_t)(kb + r) * G4 + nb + tx];
    __syncthreads();
#pragma unroll
    for (int r = ty; r < 32; r += 8) {
        float v = t[tx][r];                         // = W[kb+tx][nb+r]
        __nv_bfloat16 h = __float2bfloat16(v);
        __nv_bfloat16 l = __float2bfloat16(v - __bfloat162float(h));
        size_t o = (size_t)(nb + r) * K + kb + tx;
        hiT[o] = h;
        loT[o] = l;
    }
}

// ---------------- tensor-core projection GEMM (bf16 3-product split) ----------------
// Y[M,2048] = X[M,K] @ W[K,2048] + bias, computed as
//   Ahi@Whi + Ahi@Wlo + Alo@Whi   (3 K-segments, fp32 accum, mma.m16n8k16.bf16)
// CTA tile 128x128, 8 warps (2m x 4n), warp tile 64x32 (4x4 mma frags).
__global__ void __launch_bounds__(256)
k_hgemm(const __nv_bfloat16* __restrict__ Ahi, const __nv_bfloat16* __restrict__ Alo,
        const __nv_bfloat16* __restrict__ BhiT, const __nv_bfloat16* __restrict__ BloT,
        const float* __restrict__ bias, float* __restrict__ Y, int K) {
    const int N = 2048;
    __shared__ __nv_bfloat16 As[128 * 40];   // [m][k], row stride 40 (pad 8)
    __shared__ __nv_bfloat16 Bs[128 * 40];   // [n][k]

    const int tid = threadIdx.x;
    const int bm = blockIdx.y * 128, bn = blockIdx.x * 128;
    const int warp = tid >> 5, lane = tid & 31;
    const int mw = (warp & 1) * 64, nw = (warp >> 1) * 32;
    const int lr = lane >> 2, lc = (lane & 3) * 2;

    const int l_row = tid >> 2;            // 0..63 (+64 for second half)
    const int l_q   = (tid & 3) * 8;       // bf16 col offset {0,8,16,24}

    float acc[4][4][4];
#pragma unroll
    for (int a = 0; a < 4; a++)
#pragma unroll
        for (int b = 0; b < 4; b++)
#pragma unroll
            for (int c = 0; c < 4; c++) acc[a][b][c] = 0.f;

    const int nk  = K >> 5;        // 32-wide chunks per segment
    const int nch = 3 * nk;        // 3 segments

    // prefetch chunk 0 (segment 0: Ahi / BhiT, k0 = 0)
    uint4 ra0 = *(const uint4*)(Ahi  + (size_t)(bm + l_row)      * K + l_q);
    uint4 ra1 = *(const uint4*)(Ahi  + (size_t)(bm + l_row + 64) * K + l_q);
    uint4 rb0 = *(const uint4*)(BhiT + (size_t)(bn + l_row)      * K + l_q);
    uint4 rb1 = *(const uint4*)(BhiT + (size_t)(bn + l_row + 64) * K + l_q);

    for (int c = 0; c < nch; ++c) {
        __syncthreads();
        *(uint4*)&As[l_row * 40 + l_q]        = ra0;
        *(uint4*)&As[(l_row + 64) * 40 + l_q] = ra1;
        *(uint4*)&Bs[l_row * 40 + l_q]        = rb0;
        *(uint4*)&Bs[(l_row + 64) * 40 + l_q] = rb1;
        __syncthreads();

        if (c + 1 < nch) {
            const int c1 = c + 1;
            const int seg = c1 / nk;
            const int k0 = (c1 - seg * nk) * 32;
            const __nv_bfloat16* Ap = (seg == 2) ? Alo  : Ahi;
            const __nv_bfloat16* Bp = (seg == 1) ? BloT : BhiT;
            ra0 = *(const uint4*)(Ap + (size_t)(bm + l_row)      * K + k0 + l_q);
            ra1 = *(const uint4*)(Ap + (size_t)(bm + l_row + 64) * K + k0 + l_q);
            rb0 = *(const uint4*)(Bp + (size_t)(bn + l_row)      * K + k0 + l_q);
            rb1 = *(const uint4*)(Bp + (size_t)(bn + l_row + 64) * K + k0 + l_q);
        }

#pragma unroll
        for (int kk = 0; kk < 32; kk += 16) {
            uint32_t af[4][4];
#pragma unroll
            for (int mf = 0; mf < 4; mf++) {
                const int r0 = (mw + mf * 16 + lr) * 40 + kk + lc;
                af[mf][0] = *(const uint32_t*)&As[r0];
                af[mf][1] = *(const uint32_t*)&As[r0 + 8 * 40];
                af[mf][2] = *(const uint32_t*)&As[r0 + 8];
                af[mf][3] = *(const uint32_t*)&As[r0 + 8 * 40 + 8];
            }
            uint32_t bfr[4][2];
#pragma unroll
            for (int nf = 0; nf < 4; nf++) {
                const int rb = (nw + nf * 8 + lr) * 40 + kk + lc;
                bfr[nf][0] = *(const uint32_t*)&Bs[rb];
                bfr[nf][1] = *(const uint32_t*)&Bs[rb + 8];
            }
#pragma unroll
            for (int mf = 0; mf < 4; mf++)
#pragma unroll
                for (int nf = 0; nf < 4; nf++) {
                    asm volatile(
                        "mma.sync.aligned.m16n8k16.row.col.f32.bf16.bf16.f32 "
                        "{%0,%1,%2,%3}, {%4,%5,%6,%7}, {%8,%9}, {%0,%1,%2,%3};"
                        : "+f"(acc[mf][nf][0]), "+f"(acc[mf][nf][1]),
                          "+f"(acc[mf][nf][2]), "+f"(acc[mf][nf][3])
                        : "r"(af[mf][0]), "r"(af[mf][1]),
                          "r"(af[mf][2]), "r"(af[mf][3]),
                          "r"(bfr[nf][0]), "r"(bfr[nf][1]));
                }
        }
    }

    // epilogue: bias + store fp32
#pragma unroll
    for (int nf = 0; nf < 4; nf++) {
        const int col = bn + nw + nf * 8 + lc;
        const float bz0 = __ldg(&bias[col]), bz1 = __ldg(&bias[col + 1]);
#pragma unroll
        for (int mf = 0; mf < 4; mf++) {
            const int row0 = bm + mw + mf * 16 + lr;
            float2 v0, v1;
            v0.x = acc[mf][nf][0] + bz0; v0.y = acc[mf][nf][1] + bz1;
            v1.x = acc[mf][nf][2] + bz0; v1.y = acc[mf][nf][3] + bz1;
            *(float2*)&Y[(size_t)row0 * N + col]       = v0;
            *(float2*)&Y[(size_t)(row0 + 8) * N + col] = v1;
        }
    }
}

// ---------------- persistent bidirectional LSTM recurrence (exact R1 layout) ----------------
__global__ void __launch_bounds__(REC_THREADS, 1)
k_rec(const float* __restrict__ xzf, const float* __restrict__ xzb,
      const float* __restrict__ Uf,  const float* __restrict__ Ub,
      float* __restrict__ hs_out, float* st_out, int layer) {
    extern __shared__ float sm[];
    float* Us = sm;               // [512][32]: k*32 + jj*4 + gate
    float* Hs = sm + 512 * 32;    // [64][HSS]

    const int dir = blockIdx.x >> 6;
    const int cid = blockIdx.x & 63;
    const float* xz = dir ? xzb : xzf;
    const float* U  = dir ? Ub  : Uf;
    int* cnt = &g_cnt[layer * 2 + dir];
    const int jbase = cid * CH;
    const int tid = threadIdx.x;

    for (int idx = tid; idx < 512 * 32; idx += REC_THREADS) {
        int k = idx >> 5, cc = idx & 31;
        int jq = cc >> 2, g = cc & 3;
        Us[idx] = U[(size_t)k * G4 + g * Hh + jbase + jq];
    }

    const int bp = tid >> 3;
    const int jj = tid & 7;
    const int b0 = bp * 2, b1 = b0 + 1;
    const int jg = jbase + jj;
    float c0 = 0.f, c1 = 0.f;

    float* HB0 = g_hbuf + (size_t)dir * 2 * Bsz * Hh;
    float* HB1 = HB0 + Bsz * Hh;
    const float* uptr = Us + jj * 4;
    __syncthreads();

    for (int s = 0; s < Tt; ++s) {
        const int tt = dir ? (Tt - 1 - s) : s;
        const float* hp = (s & 1) ? HB1 : HB0;
        float*       hn = (s & 1) ? HB0 : HB1;

        for (int idx = tid * 4; idx < Bsz * Hh; idx += REC_THREADS * 4) {
            float4 v = __ldcg((const float4*)(hp + idx));
            int b = idx >> 9, k = idx & 511;
            *(float4*)&Hs[b * HSS + k] = v;
        }
        __syncthreads();

        const float* xzp = xz + (size_t)tt * G4 + jg;
        size_t o0 = (size_t)b0 * Tt * G4, o1 = (size_t)b1 * Tt * G4;
        unsigned long long a001 = pack2(__ldcs(xzp + o0),        __ldcs(xzp + o0 + 512));
        unsigned long long a023 = pack2(__ldcs(xzp + o0 + 1024), __ldcs(xzp + o0 + 1536));
        unsigned long long a101 = pack2(__ldcs(xzp + o1),        __ldcs(xzp + o1 + 512));
        unsigned long long a123 = pack2(__ldcs(xzp + o1 + 1024), __ldcs(xzp + o1 + 1536));

#pragma unroll 8
        for (int k = 0; k < Hh; ++k) {
            float h0 = Hs[b0 * HSS + k];
            float h1 = Hs[b1 * HSS + k];
            ulonglong2 uu = *(const ulonglong2*)(uptr + k * 32);
            unsigned long long h00 = dup2(h0), h11 = dup2(h1);
            fma2(a001, h00, uu.x); fma2(a023, h00, uu.y);
            fma2(a101, h11, uu.x); fma2(a123, h11, uu.y);
        }

        float2 zif0 = unpack2(a001), zgo0 = unpack2(a023);
        float2 zif1 = unpack2(a101), zgo1 = unpack2(a123);
        float i0 = sigm(zif0.x), f0 = sigm(zif0.y);
        float gg0 = tanhf(zgo0.x), og0 = sigm(zgo0.y);
        c0 = f0 * c0 + i0 * gg0;
        float h0n = og0 * tanhf(c0);
        float i1 = sigm(zif1.x), f1 = sigm(zif1.y);
        float gg1 = tanhf(zgo1.x), og1 = sigm(zgo1.y);
        c1 = f1 * c1 + i1 * gg1;
        float h1n = og1 * tanhf(c1);

        hn[b0 * Hh + jg] = h0n;
        hn[b1 * Hh + jg] = h1n;
        hs_out[((size_t)b0 * Tt + tt) * 1024 + dir * Hh + jg] = h0n;
        hs_out[((size_t)b1 * Tt + tt) * 1024 + dir * Hh + jg] = h1n;
        if (st_out != nullptr && s == Tt - 1) {
            st_out[b0 * 1024 + dir * Hh + jg] = h0n;
            st_out[b1 * 1024 + dir * Hh + jg] = h1n;
            st_out[Bsz * 1024 + b0 * 1024 + dir * Hh + jg] = c0;
            st_out[Bsz * 1024 + b1 * 1024 + dir * Hh + jg] = c1;
        }

        __threadfence();
        __syncthreads();
        if (tid == 0) {
            atomicAdd(cnt, 1);
            const int target = NC * (s + 1);
            while (*(volatile int*)cnt < target) __nanosleep(32);
        }
        __syncthreads();
        __threadfence();
    }
}

// ---------------- launch sequence ----------------
extern "C" void kernel_launch(void* const* d_in, const int* in_sizes, int n_in,
                              void* d_out, int out_size) {
    const int*   ids = (const int*)d_in[0];
    const float* emb = (const float*)d_in[1];
    const float *W1f = (const float*)d_in[2],  *U1f = (const float*)d_in[3],
                *b1f = (const float*)d_in[4];
    const float *W1b = (const float*)d_in[5],  *U1b = (const float*)d_in[6],
                *b1b = (const float*)d_in[7];
    const float *W2f = (const float*)d_in[8],  *U2f = (const float*)d_in[9],
                *b2f = (const float*)d_in[10];
    const float *W2b = (const float*)d_in[11], *U2b = (const float*)d_in[12],
                *b2b = (const float*)d_in[13];
    float* out = (float*)d_out;

    float *px, *pxz0, *pxz1, *pl1;
    __nv_bfloat16 *pahi, *palo, *pwhi, *pwlo;
    cudaGetSymbolAddress((void**)&px,   g_x);
    cudaGetSymbolAddress((void**)&pxz0, g_xz0);
    cudaGetSymbolAddress((void**)&pxz1, g_xz1);
    cudaGetSymbolAddress((void**)&pl1,  g_l1);
    cudaGetSymbolAddress((void**)&pahi, g_ahi);
    cudaGetSymbolAddress((void**)&palo, g_alo);
    cudaGetSymbolAddress((void**)&pwhi, g_whiT);
    cudaGetSymbolAddress((void**)&pwlo, g_wloT);

    cudaFuncSetAttribute(k_rec, cudaFuncAttributeMaxDynamicSharedMemorySize, REC_SMEM);

    k_init<<<128, 256>>>(1);
    k_gather<<<16384, 256>>>(ids, emb);

    const dim3 gg(G4 / 128, (Bsz * Tt) / 128);   // (16, 256)
    const dim3 tw(32, 8);

    // ----- layer 1 (K = 512) -----
    {
        const int K = Ee;
        const int n4 = Bsz * Tt * K / 4;
        k_splitA<<<(n4 + 255) / 256, 256>>>(px, pahi, palo, n4);
        k_splitW<<<dim3(G4 / 32, K / 32), tw>>>(W1f, pwhi, pwlo, K);
        k_hgemm<<<gg, 256>>>(pahi, palo, pwhi, pwlo, b1f, pxz0, K);
        k_splitW<<<dim3(G4 / 32, K / 32), tw>>>(W1b, pwhi, pwlo, K);
        k_hgemm<<<gg, 256>>>(pahi, palo, pwhi, pwlo, b1b, pxz1, K);
    }
    k_rec<<<2 * NC, REC_THREADS, REC_SMEM>>>(pxz0, pxz1, U1f, U1b, pl1, nullptr, 0);
    k_init<<<128, 256>>>(0);

    // ----- layer 2 (K = 1024) -----
    {
        const int K = 2 * Hh;
        const int n4 = Bsz * Tt * K / 4;
        k_splitA<<<(n4 + 255) / 256, 256>>>(pl1, pahi, palo, n4);
        k_splitW<<<dim3(G4 / 32, K / 32), tw>>>(W2f, pwhi, pwlo, K);
        k_hgemm<<<gg, 256>>>(pahi, palo, pwhi, pwlo, b2f, pxz0, K);
        k_splitW<<<dim3(G4 / 32, K / 32), tw>>>(W2b, pwhi, pwlo, K);
        k_hgemm<<<gg, 256>>>(pahi, palo, pwhi, pwlo, b2b, pxz1, K);
    }
    k_rec<<<2 * NC, REC_THREADS, REC_SMEM>>>(pxz0, pxz1, U2f, U2b, out,
                                             out + (size_t)Bsz * Tt * 1024, 1);
}

// round 6
// speedup vs baseline: 3.8016x; 1.5355x over previous
#include <cuda_runtime.h>
#include <cuda_bf16.h>
#include <cstdint>

// Problem constants
#define Bsz 64
#define Tt  512
#define Ee  512
#define Hh  512
#define G4  2048          // 4*H
#define NC  64            // CTAs per direction in recurrence
#define AROW 520          // SMEM row stride (bf16 elems): 260 words % 32 == 4 -> ldmatrix conflict-free
#define ZST 34            // z SMEM row stride (floats, even -> aligned float2)
#define REC_THREADS 256
#define REC_SMEM (192*AROW*2 + 64*ZST*4)   // A(2x64) + U(2x32) rows bf16  +  z fp32

// ---------------- scratch (static device memory; no allocation) ----------------
__device__ float g_x  [(size_t)Bsz*Tt*Ee];
__device__ float g_xz0[(size_t)Bsz*Tt*G4];
__device__ float g_xz1[(size_t)Bsz*Tt*G4];
__device__ float g_l1 [(size_t)Bsz*Tt*2*Hh];
__device__ __nv_bfloat16 g_hh[2*2*Bsz*Hh];        // [dir][parity][b][512] h hi
__device__ __nv_bfloat16 g_hl[2*2*Bsz*Hh];        // [dir][parity][b][512] h lo
__device__ int   g_cnt[4];                        // per (layer,dir) barrier counters
// bf16 split buffers for tensor-core projections
__device__ __nv_bfloat16 g_ahi [(size_t)Bsz*Tt*1024];
__device__ __nv_bfloat16 g_alo [(size_t)Bsz*Tt*1024];
__device__ __nv_bfloat16 g_whiT[(size_t)G4*1024];
__device__ __nv_bfloat16 g_wloT[(size_t)G4*1024];

__device__ __forceinline__ float sigm(float x) { return 1.0f / (1.0f + expf(-x)); }

__device__ __forceinline__ void cpasync16(uint32_t dst, const void* src) {
    asm volatile("cp.async.cg.shared.global [%0], [%1], 16;" :: "r"(dst), "l"(src));
}

#define LDSM4(r, addr)                                                         \
    asm volatile("ldmatrix.sync.aligned.m8n8.x4.shared.b16 {%0,%1,%2,%3}, [%4];" \
                 : "=r"((r)[0]), "=r"((r)[1]), "=r"((r)[2]), "=r"((r)[3])      \
                 : "r"(addr))

#define MMA16816(acc, a, b0, b1)                                               \
    asm volatile("mma.sync.aligned.m16n8k16.row.col.f32.bf16.bf16.f32 "        \
                 "{%0,%1,%2,%3}, {%4,%5,%6,%7}, {%8,%9}, {%0,%1,%2,%3};"       \
                 : "+f"((acc)[0]), "+f"((acc)[1]), "+f"((acc)[2]), "+f"((acc)[3]) \
                 : "r"((a)[0]), "r"((a)[1]), "r"((a)[2]), "r"((a)[3]),         \
                   "r"(b0), "r"(b1))

// ---------------- init: zero bf16 h buffers (+ counters) ----------------
__global__ void k_init(int full) {
    int i = blockIdx.x * blockDim.x + threadIdx.x;
    uint4 z = make_uint4(0, 0, 0, 0);
    if (i < 16384) {                 // 2*2*64*512 bf16 = 16384 uint4 per buffer
        ((uint4*)g_hh)[i] = z;
        ((uint4*)g_hl)[i] = z;
    }
    if (full && i < 4) g_cnt[i] = 0;
}

// ---------------- embedding gather ----------------
__global__ void k_gather(const int* __restrict__ ids, const float* __restrict__ emb) {
    int i = blockIdx.x * blockDim.x + threadIdx.x;
    int bt = i >> 7;
    int c  = i & 127;
    int id = __ldg(&ids[bt]);
    ((float4*)g_x)[i] = __ldg((const float4*)emb + (size_t)id * 128 + c);
}

// ---------------- A split: fp32 -> bf16 hi + lo ----------------
__global__ void k_splitA(const float* __restrict__ X, __nv_bfloat16* __restrict__ hi,
                         __nv_bfloat16* __restrict__ lo, int n4) {
    int i = blockIdx.x * blockDim.x + threadIdx.x;
    if (i >= n4) return;
    float4 v = __ldcs((const float4*)X + i);
    __nv_bfloat16 h0 = __float2bfloat16(v.x), h1 = __float2bfloat16(v.y);
    __nv_bfloat16 h2 = __float2bfloat16(v.z), h3 = __float2bfloat16(v.w);
    __nv_bfloat16 l0 = __float2bfloat16(v.x - __bfloat162float(h0));
    __nv_bfloat16 l1 = __float2bfloat16(v.y - __bfloat162float(h1));
    __nv_bfloat16 l2 = __float2bfloat16(v.z - __bfloat162float(h2));
    __nv_bfloat16 l3 = __float2bfloat16(v.w - __bfloat162float(h3));
    ((__nv_bfloat162*)hi)[i*2]   = __nv_bfloat162(h0, h1);
    ((__nv_bfloat162*)hi)[i*2+1] = __nv_bfloat162(h2, h3);
    ((__nv_bfloat162*)lo)[i*2]   = __nv_bfloat162(l0, l1);
    ((__nv_bfloat162*)lo)[i*2+1] = __nv_bfloat162(l2, l3);
}

// ---------------- W split + transpose ----------------
__global__ void __launch_bounds__(256)
k_splitW(const float* __restrict__ W, __nv_bfloat16* __restrict__ hiT,
         __nv_bfloat16* __restrict__ loT, int K) {
    __shared__ float t[32][33];
    const int kb = blockIdx.y * 32, nb = blockIdx.x * 32;
    const int tx = threadIdx.x, ty = threadIdx.y;
#pragma unroll
    for (int r = ty; r < 32; r += 8)
        t[r][tx] = W[(size_t)(kb + r) * G4 + nb + tx];
    __syncthreads();
#pragma unroll
    for (int r = ty; r < 32; r += 8) {
        float v = t[tx][r];
        __nv_bfloat16 h = __float2bfloat16(v);
        __nv_bfloat16 l = __float2bfloat16(v - __bfloat162float(h));
        size_t o = (size_t)(nb + r) * K + kb + tx;
        hiT[o] = h;
        loT[o] = l;
    }
}

// ---------------- tensor-core projection GEMM (bf16 3-product split) ----------------
__global__ void __launch_bounds__(256)
k_hgemm(const __nv_bfloat16* __restrict__ Ahi, const __nv_bfloat16* __restrict__ Alo,
        const __nv_bfloat16* __restrict__ BhiT, const __nv_bfloat16* __restrict__ BloT,
        const float* __restrict__ bias, float* __restrict__ Y, int K) {
    const int N = 2048;
    __shared__ __nv_bfloat16 As[128 * 40];
    __shared__ __nv_bfloat16 Bs[128 * 40];

    const int tid = threadIdx.x;
    const int bm = blockIdx.y * 128, bn = blockIdx.x * 128;
    const int warp = tid >> 5, lane = tid & 31;
    const int mw = (warp & 1) * 64, nw = (warp >> 1) * 32;
    const int lr = lane >> 2, lc = (lane & 3) * 2;

    const int l_row = tid >> 2;
    const int l_q   = (tid & 3) * 8;

    float acc[4][4][4];
#pragma unroll
    for (int a = 0; a < 4; a++)
#pragma unroll
        for (int b = 0; b < 4; b++)
#pragma unroll
            for (int c = 0; c < 4; c++) acc[a][b][c] = 0.f;

    const int nk  = K >> 5;
    const int nch = 3 * nk;

    uint4 ra0 = *(const uint4*)(Ahi  + (size_t)(bm + l_row)      * K + l_q);
    uint4 ra1 = *(const uint4*)(Ahi  + (size_t)(bm + l_row + 64) * K + l_q);
    uint4 rb0 = *(const uint4*)(BhiT + (size_t)(bn + l_row)      * K + l_q);
    uint4 rb1 = *(const uint4*)(BhiT + (size_t)(bn + l_row + 64) * K + l_q);

    for (int c = 0; c < nch; ++c) {
        __syncthreads();
        *(uint4*)&As[l_row * 40 + l_q]        = ra0;
        *(uint4*)&As[(l_row + 64) * 40 + l_q] = ra1;
        *(uint4*)&Bs[l_row * 40 + l_q]        = rb0;
        *(uint4*)&Bs[(l_row + 64) * 40 + l_q] = rb1;
        __syncthreads();

        if (c + 1 < nch) {
            const int c1 = c + 1;
            const int seg = c1 / nk;
            const int k0 = (c1 - seg * nk) * 32;
            const __nv_bfloat16* Ap = (seg == 2) ? Alo  : Ahi;
            const __nv_bfloat16* Bp = (seg == 1) ? BloT : BhiT;
            ra0 = *(const uint4*)(Ap + (size_t)(bm + l_row)      * K + k0 + l_q);
            ra1 = *(const uint4*)(Ap + (size_t)(bm + l_row + 64) * K + k0 + l_q);
            rb0 = *(const uint4*)(Bp + (size_t)(bn + l_row)      * K + k0 + l_q);
            rb1 = *(const uint4*)(Bp + (size_t)(bn + l_row + 64) * K + k0 + l_q);
        }

#pragma unroll
        for (int kk = 0; kk < 32; kk += 16) {
            uint32_t af[4][4];
#pragma unroll
            for (int mf = 0; mf < 4; mf++) {
                const int r0 = (mw + mf * 16 + lr) * 40 + kk + lc;
                af[mf][0] = *(const uint32_t*)&As[r0];
                af[mf][1] = *(const uint32_t*)&As[r0 + 8 * 40];
                af[mf][2] = *(const uint32_t*)&As[r0 + 8];
                af[mf][3] = *(const uint32_t*)&As[r0 + 8 * 40 + 8];
            }
            uint32_t bfr[4][2];
#pragma unroll
            for (int nf = 0; nf < 4; nf++) {
                const int rb = (nw + nf * 8 + lr) * 40 + kk + lc;
                bfr[nf][0] = *(const uint32_t*)&Bs[rb];
                bfr[nf][1] = *(const uint32_t*)&Bs[rb + 8];
            }
#pragma unroll
            for (int mf = 0; mf < 4; mf++)
#pragma unroll
                for (int nf = 0; nf < 4; nf++)
                    MMA16816(acc[mf][nf], af[mf], bfr[nf][0], bfr[nf][1]);
        }
    }

#pragma unroll
    for (int nf = 0; nf < 4; nf++) {
        const int col = bn + nw + nf * 8 + lc;
        const float bz0 = __ldg(&bias[col]), bz1 = __ldg(&bias[col + 1]);
#pragma unroll
        for (int mf = 0; mf < 4; mf++) {
            const int row0 = bm + mw + mf * 16 + lr;
            float2 v0, v1;
            v0.x = acc[mf][nf][0] + bz0; v0.y = acc[mf][nf][1] + bz1;
            v1.x = acc[mf][nf][2] + bz0; v1.y = acc[mf][nf][3] + bz1;
            *(float2*)&Y[(size_t)row0 * N + col]       = v0;
            *(float2*)&Y[(size_t)(row0 + 8) * N + col] = v1;
        }
    }
}

// ---------------- persistent bidirectional LSTM recurrence (tensor-core) ----------------
// 128 CTAs: dir = blockIdx/64, hidden chunk cid = blockIdx%64 (8 units -> 32 gate cols).
// Per step: Z[64,32] = h[64,512] @ Uslice[512,32] via mma.bf16 3-product split.
// U split hi/lo resident in SMEM; h broadcast via L2 as bf16 hi/lo pair, staged
// with one cp.async group; z -> SMEM; epilogue thread = (batch, 2 units), c in regs.
__global__ void __launch_bounds__(REC_THREADS, 1)
k_rec(const float* __restrict__ xzf, const float* __restrict__ xzb,
      const float* __restrict__ Uf,  const float* __restrict__ Ub,
      float* __restrict__ hs_out, float* st_out, int layer) {
    extern __shared__ __nv_bfloat16 smb[];
    __nv_bfloat16* Ahi = smb;                  // [64][AROW]
    __nv_bfloat16* Alo = Ahi + 64 * AROW;      // [64][AROW]
    __nv_bfloat16* Uhi = Alo + 64 * AROW;      // [32][AROW]
    __nv_bfloat16* Ulo = Uhi + 32 * AROW;      // [32][AROW]
    float* zf = (float*)(Ulo + 32 * AROW);     // [64][ZST]

    const int dir = blockIdx.x >> 6;
    const int cid = blockIdx.x & 63;
    const float* xz = dir ? xzb : xzf;
    const float* U  = dir ? Ub  : Uf;
    int* cnt = &g_cnt[layer * 2 + dir];
    const int jbase = cid * 8;
    const int tid = threadIdx.x;
    const int lane = tid & 31, warp = tid >> 5;

    // pack U slice -> bf16 hi/lo: Us[n = gate*8 + jj][k]
    for (int idx = tid; idx < 512 * 32; idx += REC_THREADS) {
        int k = idx >> 5, n = idx & 31;
        float v = U[(size_t)k * G4 + (n >> 3) * Hh + jbase + (n & 7)];
        __nv_bfloat16 h = __float2bfloat16(v);
        Uhi[n * AROW + k] = h;
        Ulo[n * AROW + k] = __float2bfloat16(v - __bfloat162float(h));
    }

    // epilogue mapping: thread -> (batch eb, units eu, eu+1)
    const int eb = tid >> 2;
    const int eu = (tid & 3) * 2;
    float c0 = 0.f, c1 = 0.f;

    // staging mapping: row sr, quarter sq; uint4 indices sq + 4i
    const int sr = tid >> 2, sq = tid & 3;

    // mma mapping: warp -> A tile mf (m16), B tiles at rows nb0, nb0+8
    const int mf  = warp & 3;
    const int nfg = warp >> 2;
    const int nb0 = nfg * 16;
    const uint32_t aoff  = (uint32_t)(((mf * 16 + (lane & 15)) * AROW + ((lane >> 4) << 3)) * 2);
    const uint32_t boff0 = (uint32_t)(((nb0 + (lane & 7)) * AROW + ((lane >> 3) << 3)) * 2);
    const uint32_t boff1 = boff0 + (uint32_t)(8 * AROW * 2);
    const uint32_t sAhi = (uint32_t)__cvta_generic_to_shared(Ahi);
    const uint32_t sAlo = (uint32_t)__cvta_generic_to_shared(Alo);
    const uint32_t sUhi = (uint32_t)__cvta_generic_to_shared(Uhi);
    const uint32_t sUlo = (uint32_t)__cvta_generic_to_shared(Ulo);

    const __nv_bfloat16* HHb = g_hh + (size_t)dir * 2 * Bsz * Hh;
    const __nv_bfloat16* HLb = g_hl + (size_t)dir * 2 * Bsz * Hh;

    __syncthreads();

    for (int s = 0; s < Tt; ++s) {
        const int tt = dir ? (Tt - 1 - s) : s;
        const int par = s & 1;
        const __nv_bfloat16* hpH = HHb + par * Bsz * Hh;
        const __nv_bfloat16* hpL = HLb + par * Bsz * Hh;
        __nv_bfloat16* hnH = (__nv_bfloat16*)HHb + (par ^ 1) * Bsz * Hh;
        __nv_bfloat16* hnL = (__nv_bfloat16*)HLb + (par ^ 1) * Bsz * Hh;

        // prefetch xz gate pre-activations (latency hides under staging + mma)
        const float* xzp = xz + ((size_t)eb * Tt + tt) * G4 + jbase;
        float x[8];
#pragma unroll
        for (int g = 0; g < 4; ++g) {
            x[g * 2]     = __ldcs(xzp + g * 512 + eu);
            x[g * 2 + 1] = __ldcs(xzp + g * 512 + eu + 1);
        }

        // stage h hi/lo (L2 -> SMEM), one cp.async group, single wait
        {
            const uint4* srcH = (const uint4*)(hpH + sr * 512);
            const uint4* srcL = (const uint4*)(hpL + sr * 512);
            const uint32_t dH = sAhi + (uint32_t)(sr * AROW * 2) + sq * 16;
            const uint32_t dL = sAlo + (uint32_t)(sr * AROW * 2) + sq * 16;
#pragma unroll
            for (int i = 0; i < 16; ++i) {
                cpasync16(dH + i * 64, srcH + sq + 4 * i);
                cpasync16(dL + i * 64, srcL + sq + 4 * i);
            }
            asm volatile("cp.async.commit_group;");
            asm volatile("cp.async.wait_group 0;" ::: "memory");
        }
        __syncthreads();

        // Z = Ahi@Uhi + Alo@Uhi + Ahi@Ulo
        float acc0[4] = {0.f, 0.f, 0.f, 0.f};
        float acc1[4] = {0.f, 0.f, 0.f, 0.f};
#pragma unroll
        for (int p = 0; p < 3; ++p) {
            const uint32_t ab  = (p == 1 ? sAlo : sAhi) + aoff;
            const uint32_t bb0 = (p == 2 ? sUlo : sUhi) + boff0;
            const uint32_t bb1 = (p == 2 ? sUlo : sUhi) + boff1;
#pragma unroll 4
            for (int kb = 0; kb < 16; ++kb) {
                const uint32_t ko = kb * 64;       // 32 bf16 * 2B
                uint32_t a0[4], a1[4], b0[4], b1[4];
                LDSM4(a0, ab + ko);
                LDSM4(a1, ab + ko + 32);
                LDSM4(b0, bb0 + ko);
                LDSM4(b1, bb1 + ko);
                MMA16816(acc0, a0, b0[0], b0[1]);
                MMA16816(acc1, a0, b1[0], b1[1]);
                MMA16816(acc0, a1, b0[2], b0[3]);
                MMA16816(acc1, a1, b1[2], b1[3]);
            }
        }

        // write z tiles to SMEM
        {
            const int lr = lane >> 2, lc = (lane & 3) * 2;
            const int zr = mf * 16 + lr;
            *(float2*)&zf[zr * ZST + nb0 + lc]           = make_float2(acc0[0], acc0[1]);
            *(float2*)&zf[(zr + 8) * ZST + nb0 + lc]     = make_float2(acc0[2], acc0[3]);
            *(float2*)&zf[zr * ZST + nb0 + 8 + lc]       = make_float2(acc1[0], acc1[1]);
            *(float2*)&zf[(zr + 8) * ZST + nb0 + 8 + lc] = make_float2(acc1[2], acc1[3]);
        }
        __syncthreads();

        // epilogue: 2 hidden units per thread
#pragma unroll
        for (int e = 0; e < 2; ++e) {
            const int u = eu + e;
            const float zi = zf[eb * ZST + u]      + x[0 + e];
            const float zF = zf[eb * ZST + 8 + u]  + x[2 + e];
            const float zg = zf[eb * ZST + 16 + u] + x[4 + e];
            const float zo = zf[eb * ZST + 24 + u] + x[6 + e];
            const float ig = sigm(zi), fg = sigm(zF);
            const float gg = tanhf(zg), og = sigm(zo);
            float& c = e ? c1 : c0;
            c = fg * c + ig * gg;
            const float hv = og * tanhf(c);

            const __nv_bfloat16 hb = __float2bfloat16(hv);
            hnH[eb * Hh + jbase + u] = hb;
            hnL[eb * Hh + jbase + u] = __float2bfloat16(hv - __bfloat162float(hb));
            hs_out[((size_t)eb * Tt + tt) * 1024 + dir * Hh + jbase + u] = hv;
            if (st_out != nullptr && s == Tt - 1) {
                st_out[eb * 1024 + dir * Hh + jbase + u] = hv;
                st_out[Bsz * 1024 + eb * 1024 + dir * Hh + jbase + u] = c;
            }
        }

        // inter-CTA step barrier (per direction)
        __threadfence();
        __syncthreads();
        if (tid == 0) {
            atomicAdd(cnt, 1);
            const int target = NC * (s + 1);
            while (*(volatile int*)cnt < target) __nanosleep(32);
        }
        __syncthreads();
        __threadfence();
    }
}

// ---------------- launch sequence ----------------
extern "C" void kernel_launch(void* const* d_in, const int* in_sizes, int n_in,
                              void* d_out, int out_size) {
    const int*   ids = (const int*)d_in[0];
    const float* emb = (const float*)d_in[1];
    const float *W1f = (const float*)d_in[2],  *U1f = (const float*)d_in[3],
                *b1f = (const float*)d_in[4];
    const float *W1b = (const float*)d_in[5],  *U1b = (const float*)d_in[6],
                *b1b = (const float*)d_in[7];
    const float *W2f = (const float*)d_in[8],  *U2f = (const float*)d_in[9],
                *b2f = (const float*)d_in[10];
    const float *W2b = (const float*)d_in[11], *U2b = (const float*)d_in[12],
                *b2b = (const float*)d_in[13];
    float* out = (float*)d_out;

    float *px, *pxz0, *pxz1, *pl1;
    __nv_bfloat16 *pahi, *palo, *pwhi, *pwlo;
    cudaGetSymbolAddress((void**)&px,   g_x);
    cudaGetSymbolAddress((void**)&pxz0, g_xz0);
    cudaGetSymbolAddress((void**)&pxz1, g_xz1);
    cudaGetSymbolAddress((void**)&pl1,  g_l1);
    cudaGetSymbolAddress((void**)&pahi, g_ahi);
    cudaGetSymbolAddress((void**)&palo, g_alo);
    cudaGetSymbolAddress((void**)&pwhi, g_whiT);
    cudaGetSymbolAddress((void**)&pwlo, g_wloT);

    cudaFuncSetAttribute(k_rec, cudaFuncAttributeMaxDynamicSharedMemorySize, REC_SMEM);

    k_init<<<128, 256>>>(1);
    k_gather<<<16384, 256>>>(ids, emb);

    const dim3 gg(G4 / 128, (Bsz * Tt) / 128);   // (16, 256)
    const dim3 tw(32, 8);

    // ----- layer 1 (K = 512) -----
    {
        const int K = Ee;
        const int n4 = Bsz * Tt * K / 4;
        k_splitA<<<(n4 + 255) / 256, 256>>>(px, pahi, palo, n4);
        k_splitW<<<dim3(G4 / 32, K / 32), tw>>>(W1f, pwhi, pwlo, K);
        k_hgemm<<<gg, 256>>>(pahi, palo, pwhi, pwlo, b1f, pxz0, K);
        k_splitW<<<dim3(G4 / 32, K / 32), tw>>>(W1b, pwhi, pwlo, K);
        k_hgemm<<<gg, 256>>>(pahi, palo, pwhi, pwlo, b1b, pxz1, K);
    }
    k_rec<<<2 * NC, REC_THREADS, REC_SMEM>>>(pxz0, pxz1, U1f, U1b, pl1, nullptr, 0);
    k_init<<<128, 256>>>(0);

    // ----- layer 2 (K = 1024) -----
    {
        const int K = 2 * Hh;
        const int n4 = Bsz * Tt * K / 4;
        k_splitA<<<(n4 + 255) / 256, 256>>>(pl1, pahi, palo, n4);
        k_splitW<<<dim3(G4 / 32, K / 32), tw>>>(W2f, pwhi, pwlo, K);
        k_hgemm<<<gg, 256>>>(pahi, palo, pwhi, pwlo, b2f, pxz0, K);
        k_splitW<<<dim3(G4 / 32, K / 32), tw>>>(W2b, pwhi, pwlo, K);
        k_hgemm<<<gg, 256>>>(pahi, palo, pwhi, pwlo, b2b, pxz1, K);
    }
    k_rec<<<2 * NC, REC_THREADS, REC_SMEM>>>(pxz0, pxz1, U2f, U2b, out,
                                             out + (size_t)Bsz * Tt * 1024, 1);
}

// round 7
// speedup vs baseline: 3.9756x; 1.0458x over previous
#include <cuda_runtime.h>
#include <cuda_bf16.h>
#include <cstdint>

// Problem constants
#define Bsz 64
#define Tt  512
#define Ee  512
#define Hh  512
#define G4  2048          // 4*H
#define NC  64            // CTAs per direction in recurrence
#define AROW 520          // SMEM row stride (bf16): 260 words % 32 == 4 -> ldmatrix conflict-free
#define ZST 34            // z SMEM row stride (floats)
#define REC_THREADS 256
#define REC_SMEM (192*AROW*2 + 64*ZST*4)   // A(2x64) + U(2x32) rows bf16  +  z fp32

// ---------------- scratch (static device memory; no allocation) ----------------
__device__ float g_x  [(size_t)Bsz*Tt*Ee];
__device__ float g_xz0[(size_t)Bsz*Tt*G4];
__device__ float g_xz1[(size_t)Bsz*Tt*G4];
__device__ float g_l1 [(size_t)Bsz*Tt*2*Hh];
__device__ __nv_bfloat16 g_hh[2*2*Bsz*Hh];        // [dir][parity][b][512] h hi
__device__ __nv_bfloat16 g_hl[2*2*Bsz*Hh];        // [dir][parity][b][512] h lo
__device__ int   g_cnt[4];                        // per (layer,dir) barrier counters
// bf16 split buffers for tensor-core projections
__device__ __nv_bfloat16 g_ahi [(size_t)Bsz*Tt*1024];
__device__ __nv_bfloat16 g_alo [(size_t)Bsz*Tt*1024];
__device__ __nv_bfloat16 g_whiT[(size_t)G4*1024];
__device__ __nv_bfloat16 g_wloT[(size_t)G4*1024];

__device__ __forceinline__ float sigm(float x) { return 1.0f / (1.0f + expf(-x)); }

__device__ __forceinline__ void cpasync16(uint32_t dst, const void* src) {
    asm volatile("cp.async.cg.shared.global [%0], [%1], 16;" :: "r"(dst), "l"(src));
}

#define LDSM4(r, addr)                                                         \
    asm volatile("ldmatrix.sync.aligned.m8n8.x4.shared.b16 {%0,%1,%2,%3}, [%4];" \
                 : "=r"((r)[0]), "=r"((r)[1]), "=r"((r)[2]), "=r"((r)[3])      \
                 : "r"(addr))

#define MMA16816(acc, a, b0, b1)                                               \
    asm volatile("mma.sync.aligned.m16n8k16.row.col.f32.bf16.bf16.f32 "        \
                 "{%0,%1,%2,%3}, {%4,%5,%6,%7}, {%8,%9}, {%0,%1,%2,%3};"       \
                 : "+f"((acc)[0]), "+f"((acc)[1]), "+f"((acc)[2]), "+f"((acc)[3]) \
                 : "r"((a)[0]), "r"((a)[1]), "r"((a)[2]), "r"((a)[3]),         \
                   "r"(b0), "r"(b1))

// ---------------- init: zero bf16 h buffers (+ counters) ----------------
__global__ void k_init(int full) {
    int i = blockIdx.x * blockDim.x + threadIdx.x;
    uint4 z = make_uint4(0, 0, 0, 0);
    if (i < 16384) {
        ((uint4*)g_hh)[i] = z;
        ((uint4*)g_hl)[i] = z;
    }
    if (full && i < 4) g_cnt[i] = 0;
}

// ---------------- embedding gather ----------------
__global__ void k_gather(const int* __restrict__ ids, const float* __restrict__ emb) {
    int i = blockIdx.x * blockDim.x + threadIdx.x;
    int bt = i >> 7;
    int c  = i & 127;
    int id = __ldg(&ids[bt]);
    ((float4*)g_x)[i] = __ldg((const float4*)emb + (size_t)id * 128 + c);
}

// ---------------- A split: fp32 -> bf16 hi + lo ----------------
__global__ void k_splitA(const float* __restrict__ X, __nv_bfloat16* __restrict__ hi,
                         __nv_bfloat16* __restrict__ lo, int n4) {
    int i = blockIdx.x * blockDim.x + threadIdx.x;
    if (i >= n4) return;
    float4 v = __ldcs((const float4*)X + i);
    __nv_bfloat16 h0 = __float2bfloat16(v.x), h1 = __float2bfloat16(v.y);
    __nv_bfloat16 h2 = __float2bfloat16(v.z), h3 = __float2bfloat16(v.w);
    __nv_bfloat16 l0 = __float2bfloat16(v.x - __bfloat162float(h0));
    __nv_bfloat16 l1 = __float2bfloat16(v.y - __bfloat162float(h1));
    __nv_bfloat16 l2 = __float2bfloat16(v.z - __bfloat162float(h2));
    __nv_bfloat16 l3 = __float2bfloat16(v.w - __bfloat162float(h3));
    ((__nv_bfloat162*)hi)[i*2]   = __nv_bfloat162(h0, h1);
    ((__nv_bfloat162*)hi)[i*2+1] = __nv_bfloat162(h2, h3);
    ((__nv_bfloat162*)lo)[i*2]   = __nv_bfloat162(l0, l1);
    ((__nv_bfloat162*)lo)[i*2+1] = __nv_bfloat162(l2, l3);
}

// ---------------- W split + transpose ----------------
__global__ void __launch_bounds__(256)
k_splitW(const float* __restrict__ W, __nv_bfloat16* __restrict__ hiT,
         __nv_bfloat16* __restrict__ loT, int K) {
    __shared__ float t[32][33];
    const int kb = blockIdx.y * 32, nb = blockIdx.x * 32;
    const int tx = threadIdx.x, ty = threadIdx.y;
#pragma unroll
    for (int r = ty; r < 32; r += 8)
        t[r][tx] = W[(size_t)(kb + r) * G4 + nb + tx];
    __syncthreads();
#pragma unroll
    for (int r = ty; r < 32; r += 8) {
        float v = t[tx][r];
        __nv_bfloat16 h = __float2bfloat16(v);
        __nv_bfloat16 l = __float2bfloat16(v - __bfloat162float(h));
        size_t o = (size_t)(nb + r) * K + kb + tx;
        hiT[o] = h;
        loT[o] = l;
    }
}

// ---------------- tensor-core projection GEMM (bf16 3-product split) ----------------
__global__ void __launch_bounds__(256)
k_hgemm(const __nv_bfloat16* __restrict__ Ahi, const __nv_bfloat16* __restrict__ Alo,
        const __nv_bfloat16* __restrict__ BhiT, const __nv_bfloat16* __restrict__ BloT,
        const float* __restrict__ bias, float* __restrict__ Y, int K) {
    const int N = 2048;
    __shared__ __nv_bfloat16 As[128 * 40];
    __shared__ __nv_bfloat16 Bs[128 * 40];

    const int tid = threadIdx.x;
    const int bm = blockIdx.y * 128, bn = blockIdx.x * 128;
    const int warp = tid >> 5, lane = tid & 31;
    const int mw = (warp & 1) * 64, nw = (warp >> 1) * 32;
    const int lr = lane >> 2, lc = (lane & 3) * 2;

    const int l_row = tid >> 2;
    const int l_q   = (tid & 3) * 8;

    float acc[4][4][4];
#pragma unroll
    for (int a = 0; a < 4; a++)
#pragma unroll
        for (int b = 0; b < 4; b++)
#pragma unroll
            for (int c = 0; c < 4; c++) acc[a][b][c] = 0.f;

    const int nk  = K >> 5;
    const int nch = 3 * nk;

    uint4 ra0 = *(const uint4*)(Ahi  + (size_t)(bm + l_row)      * K + l_q);
    uint4 ra1 = *(const uint4*)(Ahi  + (size_t)(bm + l_row + 64) * K + l_q);
    uint4 rb0 = *(const uint4*)(BhiT + (size_t)(bn + l_row)      * K + l_q);
    uint4 rb1 = *(const uint4*)(BhiT + (size_t)(bn + l_row + 64) * K + l_q);

    for (int c = 0; c < nch; ++c) {
        __syncthreads();
        *(uint4*)&As[l_row * 40 + l_q]        = ra0;
        *(uint4*)&As[(l_row + 64) * 40 + l_q] = ra1;
        *(uint4*)&Bs[l_row * 40 + l_q]        = rb0;
        *(uint4*)&Bs[(l_row + 64) * 40 + l_q] = rb1;
        __syncthreads();

        if (c + 1 < nch) {
            const int c1 = c + 1;
            const int seg = c1 / nk;
            const int k0 = (c1 - seg * nk) * 32;
            const __nv_bfloat16* Ap = (seg == 2) ? Alo  : Ahi;
            const __nv_bfloat16* Bp = (seg == 1) ? BloT : BhiT;
            ra0 = *(const uint4*)(Ap + (size_t)(bm + l_row)      * K + k0 + l_q);
            ra1 = *(const uint4*)(Ap + (size_t)(bm + l_row + 64) * K + k0 + l_q);
            rb0 = *(const uint4*)(Bp + (size_t)(bn + l_row)      * K + k0 + l_q);
            rb1 = *(const uint4*)(Bp + (size_t)(bn + l_row + 64) * K + k0 + l_q);
        }

#pragma unroll
        for (int kk = 0; kk < 32; kk += 16) {
            uint32_t af[4][4];
#pragma unroll
            for (int mf = 0; mf < 4; mf++) {
                const int r0 = (mw + mf * 16 + lr) * 40 + kk + lc;
                af[mf][0] = *(const uint32_t*)&As[r0];
                af[mf][1] = *(const uint32_t*)&As[r0 + 8 * 40];
                af[mf][2] = *(const uint32_t*)&As[r0 + 8];
                af[mf][3] = *(const uint32_t*)&As[r0 + 8 * 40 + 8];
            }
            uint32_t bfr[4][2];
#pragma unroll
            for (int nf = 0; nf < 4; nf++) {
                const int rb = (nw + nf * 8 + lr) * 40 + kk + lc;
                bfr[nf][0] = *(const uint32_t*)&Bs[rb];
                bfr[nf][1] = *(const uint32_t*)&Bs[rb + 8];
            }
#pragma unroll
            for (int mf = 0; mf < 4; mf++)
#pragma unroll
                for (int nf = 0; nf < 4; nf++)
                    MMA16816(acc[mf][nf], af[mf], bfr[nf][0], bfr[nf][1]);
        }
    }

#pragma unroll
    for (int nf = 0; nf < 4; nf++) {
        const int col = bn + nw + nf * 8 + lc;
        const float bz0 = __ldg(&bias[col]), bz1 = __ldg(&bias[col + 1]);
#pragma unroll
        for (int mf = 0; mf < 4; mf++) {
            const int row0 = bm + mw + mf * 16 + lr;
            float2 v0, v1;
            v0.x = acc[mf][nf][0] + bz0; v0.y = acc[mf][nf][1] + bz1;
            v1.x = acc[mf][nf][2] + bz0; v1.y = acc[mf][nf][3] + bz1;
            *(float2*)&Y[(size_t)row0 * N + col]       = v0;
            *(float2*)&Y[(size_t)(row0 + 8) * N + col] = v1;
        }
    }
}

// ---------------- persistent bidirectional LSTM recurrence (tensor-core, overlapped) ---
// Same skeleton as R6 winner. Changes:
//  * staging split into 2 cp.async groups (hi, lo); Ahi-dependent products run
//    while the lo group is still in flight.
//  * barrier poll = pure ld.acquire.gpu spin (no nanosleep, no trailing fence).
__global__ void __launch_bounds__(REC_THREADS, 1)
k_rec(const float* __restrict__ xzf, const float* __restrict__ xzb,
      const float* __restrict__ Uf,  const float* __restrict__ Ub,
      float* __restrict__ hs_out, float* st_out, int layer) {
    extern __shared__ __nv_bfloat16 smb[];
    __nv_bfloat16* Ahi = smb;                  // [64][AROW]
    __nv_bfloat16* Alo = Ahi + 64 * AROW;      // [64][AROW]
    __nv_bfloat16* Uhi = Alo + 64 * AROW;      // [32][AROW]
    __nv_bfloat16* Ulo = Uhi + 32 * AROW;      // [32][AROW]
    float* zf = (float*)(Ulo + 32 * AROW);     // [64][ZST]

    const int dir = blockIdx.x >> 6;
    const int cid = blockIdx.x & 63;
    const float* xz = dir ? xzb : xzf;
    const float* U  = dir ? Ub  : Uf;
    int* cnt = &g_cnt[layer * 2 + dir];
    const int jbase = cid * 8;
    const int tid = threadIdx.x;
    const int lane = tid & 31, warp = tid >> 5;

    // pack U slice -> bf16 hi/lo: Us[n = gate*8 + jj][k]
    for (int idx = tid; idx < 512 * 32; idx += REC_THREADS) {
        int k = idx >> 5, n = idx & 31;
        float v = U[(size_t)k * G4 + (n >> 3) * Hh + jbase + (n & 7)];
        __nv_bfloat16 h = __float2bfloat16(v);
        Uhi[n * AROW + k] = h;
        Ulo[n * AROW + k] = __float2bfloat16(v - __bfloat162float(h));
    }

    const int eb = tid >> 2;
    const int eu = (tid & 3) * 2;
    float c0 = 0.f, c1 = 0.f;

    const int sr = tid >> 2, sq = tid & 3;

    const int mf  = warp & 3;
    const int nfg = warp >> 2;
    const int nb0 = nfg * 16;
    const uint32_t aoff  = (uint32_t)(((mf * 16 + (lane & 15)) * AROW + ((lane >> 4) << 3)) * 2);
    const uint32_t boff0 = (uint32_t)(((nb0 + (lane & 7)) * AROW + ((lane >> 3) << 3)) * 2);
    const uint32_t boff1 = boff0 + (uint32_t)(8 * AROW * 2);
    const uint32_t sAhi = (uint32_t)__cvta_generic_to_shared(Ahi);
    const uint32_t sAlo = (uint32_t)__cvta_generic_to_shared(Alo);
    const uint32_t sUhi = (uint32_t)__cvta_generic_to_shared(Uhi);
    const uint32_t sUlo = (uint32_t)__cvta_generic_to_shared(Ulo);

    const __nv_bfloat16* HHb = g_hh + (size_t)dir * 2 * Bsz * Hh;
    const __nv_bfloat16* HLb = g_hl + (size_t)dir * 2 * Bsz * Hh;

    __syncthreads();

    for (int s = 0; s < Tt; ++s) {
        const int tt = dir ? (Tt - 1 - s) : s;
        const int par = s & 1;
        const __nv_bfloat16* hpH = HHb + par * Bsz * Hh;
        const __nv_bfloat16* hpL = HLb + par * Bsz * Hh;
        __nv_bfloat16* hnH = (__nv_bfloat16*)HHb + (par ^ 1) * Bsz * Hh;
        __nv_bfloat16* hnL = (__nv_bfloat16*)HLb + (par ^ 1) * Bsz * Hh;

        // prefetch xz gate pre-activations
        const float* xzp = xz + ((size_t)eb * Tt + tt) * G4 + jbase;
        float x[8];
#pragma unroll
        for (int g = 0; g < 4; ++g) {
            x[g * 2]     = __ldcs(xzp + g * 512 + eu);
            x[g * 2 + 1] = __ldcs(xzp + g * 512 + eu + 1);
        }

        // stage h hi (group 0), then h lo (group 1)
        {
            const uint4* srcH = (const uint4*)(hpH + sr * 512);
            const uint4* srcL = (const uint4*)(hpL + sr * 512);
            const uint32_t dH = sAhi + (uint32_t)(sr * AROW * 2) + sq * 16;
            const uint32_t dL = sAlo + (uint32_t)(sr * AROW * 2) + sq * 16;
#pragma unroll
            for (int i = 0; i < 16; ++i) cpasync16(dH + i * 64, srcH + sq + 4 * i);
            asm volatile("cp.async.commit_group;");
#pragma unroll
            for (int i = 0; i < 16; ++i) cpasync16(dL + i * 64, srcL + sq + 4 * i);
            asm volatile("cp.async.commit_group;");
        }

        float acc0[4] = {0.f, 0.f, 0.f, 0.f};
        float acc1[4] = {0.f, 0.f, 0.f, 0.f};

        // ---- wait hi group; run Ahi@Uhi and Ahi@Ulo while lo group flies ----
        asm volatile("cp.async.wait_group 1;" ::: "memory");
        __syncthreads();
#pragma unroll
        for (int p = 0; p < 2; ++p) {
            const uint32_t ab  = sAhi + aoff;
            const uint32_t bb0 = (p == 1 ? sUlo : sUhi) + boff0;
            const uint32_t bb1 = (p == 1 ? sUlo : sUhi) + boff1;
#pragma unroll 4
            for (int kb = 0; kb < 16; ++kb) {
                const uint32_t ko = kb * 64;
                uint32_t a0[4], a1[4], b0[4], b1[4];
                LDSM4(a0, ab + ko);
                LDSM4(a1, ab + ko + 32);
                LDSM4(b0, bb0 + ko);
                LDSM4(b1, bb1 + ko);
                MMA16816(acc0, a0, b0[0], b0[1]);
                MMA16816(acc1, a0, b1[0], b1[1]);
                MMA16816(acc0, a1, b0[2], b0[3]);
                MMA16816(acc1, a1, b1[2], b1[3]);
            }
        }
        // ---- wait lo group; run Alo@Uhi ----
        asm volatile("cp.async.wait_group 0;" ::: "memory");
        __syncthreads();
        {
            const uint32_t ab  = sAlo + aoff;
            const uint32_t bb0 = sUhi + boff0;
            const uint32_t bb1 = sUhi + boff1;
#pragma unroll 4
            for (int kb = 0; kb < 16; ++kb) {
                const uint32_t ko = kb * 64;
                uint32_t a0[4], a1[4], b0[4], b1[4];
                LDSM4(a0, ab + ko);
                LDSM4(a1, ab + ko + 32);
                LDSM4(b0, bb0 + ko);
                LDSM4(b1, bb1 + ko);
                MMA16816(acc0, a0, b0[0], b0[1]);
                MMA16816(acc1, a0, b1[0], b1[1]);
                MMA16816(acc0, a1, b0[2], b0[3]);
                MMA16816(acc1, a1, b1[2], b1[3]);
            }
        }

        // write z tiles to SMEM
        {
            const int lr = lane >> 2, lc = (lane & 3) * 2;
            const int zr = mf * 16 + lr;
            *(float2*)&zf[zr * ZST + nb0 + lc]           = make_float2(acc0[0], acc0[1]);
            *(float2*)&zf[(zr + 8) * ZST + nb0 + lc]     = make_float2(acc0[2], acc0[3]);
            *(float2*)&zf[zr * ZST + nb0 + 8 + lc]       = make_float2(acc1[0], acc1[1]);
            *(float2*)&zf[(zr + 8) * ZST + nb0 + 8 + lc] = make_float2(acc1[2], acc1[3]);
        }
        __syncthreads();

        // epilogue: 2 hidden units per thread
#pragma unroll
        for (int e = 0; e < 2; ++e) {
            const int u = eu + e;
            const float zi = zf[eb * ZST + u]      + x[0 + e];
            const float zF = zf[eb * ZST + 8 + u]  + x[2 + e];
            const float zg = zf[eb * ZST + 16 + u] + x[4 + e];
            const float zo = zf[eb * ZST + 24 + u] + x[6 + e];
            const float ig = sigm(zi), fg = sigm(zF);
            const float gg = tanhf(zg), og = sigm(zo);
            float& c = e ? c1 : c0;
            c = fg * c + ig * gg;
            const float hv = og * tanhf(c);

            const __nv_bfloat16 hb = __float2bfloat16(hv);
            hnH[eb * Hh + jbase + u] = hb;
            hnL[eb * Hh + jbase + u] = __float2bfloat16(hv - __bfloat162float(hb));
            hs_out[((size_t)eb * Tt + tt) * 1024 + dir * Hh + jbase + u] = hv;
            if (st_out != nullptr && s == Tt - 1) {
                st_out[eb * 1024 + dir * Hh + jbase + u] = hv;
                st_out[Bsz * 1024 + eb * 1024 + dir * Hh + jbase + u] = c;
            }
        }

        // inter-CTA step barrier: fence + count, acquire-spin (no nanosleep)
        __threadfence();
        __syncthreads();
        if (tid == 0) {
            atomicAdd(cnt, 1);
            const int target = NC * (s + 1);
            int v;
            do {
                asm volatile("ld.acquire.gpu.global.s32 %0, [%1];"
                             : "=r"(v) : "l"(cnt) : "memory");
            } while (v < target);
        }
        __syncthreads();
    }
}

// ---------------- launch sequence ----------------
extern "C" void kernel_launch(void* const* d_in, const int* in_sizes, int n_in,
                              void* d_out, int out_size) {
    const int*   ids = (const int*)d_in[0];
    const float* emb = (const float*)d_in[1];
    const float *W1f = (const float*)d_in[2],  *U1f = (const float*)d_in[3],
                *b1f = (const float*)d_in[4];
    const float *W1b = (const float*)d_in[5],  *U1b = (const float*)d_in[6],
                *b1b = (const float*)d_in[7];
    const float *W2f = (const float*)d_in[8],  *U2f = (const float*)d_in[9],
                *b2f = (const float*)d_in[10];
    const float *W2b = (const float*)d_in[11], *U2b = (const float*)d_in[12],
                *b2b = (const float*)d_in[13];
    float* out = (float*)d_out;

    float *px, *pxz0, *pxz1, *pl1;
    __nv_bfloat16 *pahi, *palo, *pwhi, *pwlo;
    cudaGetSymbolAddress((void**)&px,   g_x);
    cudaGetSymbolAddress((void**)&pxz0, g_xz0);
    cudaGetSymbolAddress((void**)&pxz1, g_xz1);
    cudaGetSymbolAddress((void**)&pl1,  g_l1);
    cudaGetSymbolAddress((void**)&pahi, g_ahi);
    cudaGetSymbolAddress((void**)&palo, g_alo);
    cudaGetSymbolAddress((void**)&pwhi, g_whiT);
    cudaGetSymbolAddress((void**)&pwlo, g_wloT);

    cudaFuncSetAttribute(k_rec, cudaFuncAttributeMaxDynamicSharedMemorySize, REC_SMEM);

    k_init<<<128, 256>>>(1);
    k_gather<<<16384, 256>>>(ids, emb);

    const dim3 gg(G4 / 128, (Bsz * Tt) / 128);   // (16, 256)
    const dim3 tw(32, 8);

    // ----- layer 1 (K = 512) -----
    {
        const int K = Ee;
        const int n4 = Bsz * Tt * K / 4;
        k_splitA<<<(n4 + 255) / 256, 256>>>(px, pahi, palo, n4);
        k_splitW<<<dim3(G4 / 32, K / 32), tw>>>(W1f, pwhi, pwlo, K);
        k_hgemm<<<gg, 256>>>(pahi, palo, pwhi, pwlo, b1f, pxz0, K);
        k_splitW<<<dim3(G4 / 32, K / 32), tw>>>(W1b, pwhi, pwlo, K);
        k_hgemm<<<gg, 256>>>(pahi, palo, pwhi, pwlo, b1b, pxz1, K);
    }
    k_rec<<<2 * NC, REC_THREADS, REC_SMEM>>>(pxz0, pxz1, U1f, U1b, pl1, nullptr, 0);
    k_init<<<128, 256>>>(0);

    // ----- layer 2 (K = 1024) -----
    {
        const int K = 2 * Hh;
        const int n4 = Bsz * Tt * K / 4;
        k_splitA<<<(n4 + 255) / 256, 256>>>(pl1, pahi, palo, n4);
        k_splitW<<<dim3(G4 / 32, K / 32), tw>>>(W2f, pwhi, pwlo, K);
        k_hgemm<<<gg, 256>>>(pahi, palo, pwhi, pwlo, b2f, pxz0, K);
        k_splitW<<<dim3(G4 / 32, K / 32), tw>>>(W2b, pwhi, pwlo, K);
        k_hgemm<<<gg, 256>>>(pahi, palo, pwhi, pwlo, b2b, pxz1, K);
    }
    k_rec<<<2 * NC, REC_THREADS, REC_SMEM>>>(pxz0, pxz1, U2f, U2b, out,
                                             out + (size_t)Bsz * Tt * 1024, 1);
}

// round 8
// speedup vs baseline: 4.1175x; 1.0357x over previous
#include <cuda_runtime.h>
#include <cuda_bf16.h>
#include <cstdint>

// Problem constants
#define Bsz 64
#define Tt  512
#define Ee  512
#define Hh  512
#define G4  2048          // 4*H
#define NC  64            // CTAs per direction in recurrence
#define AROW 520          // SMEM row stride (bf16): 260 words % 32 == 4 -> ldmatrix conflict-free
#define ZST 34            // z SMEM row stride (floats)
#define REC_THREADS 256
#define REC_SMEM (192*AROW*2 + 64*ZST*4)   // A(2x64) + U(2x32) rows bf16  +  z fp32

// ---------------- scratch (static device memory; no allocation) ----------------
__device__ float g_xz0[(size_t)Bsz*Tt*G4];
__device__ float g_xz1[(size_t)Bsz*Tt*G4];
__device__ __nv_bfloat16 g_hh[2*2*Bsz*Hh];        // [dir][parity][b][512] h hi
__device__ __nv_bfloat16 g_hl[2*2*Bsz*Hh];        // [dir][parity][b][512] h lo
__device__ int   g_cnt[4];                        // per (layer,dir) barrier counters
// bf16 split buffers for tensor-core projections
__device__ __nv_bfloat16 g_ahi [(size_t)Bsz*Tt*1024];
__device__ __nv_bfloat16 g_alo [(size_t)Bsz*Tt*1024];
__device__ __nv_bfloat16 g_whiT[(size_t)G4*1024];
__device__ __nv_bfloat16 g_wloT[(size_t)G4*1024];

__device__ __forceinline__ float sigm(float x) { return 1.0f / (1.0f + expf(-x)); }

__device__ __forceinline__ void cpasync16(uint32_t dst, const void* src) {
    asm volatile("cp.async.cg.shared.global [%0], [%1], 16;" :: "r"(dst), "l"(src));
}

#define LDSM4(r, addr)                                                         \
    asm volatile("ldmatrix.sync.aligned.m8n8.x4.shared.b16 {%0,%1,%2,%3}, [%4];" \
                 : "=r"((r)[0]), "=r"((r)[1]), "=r"((r)[2]), "=r"((r)[3])      \
                 : "r"(addr))

#define MMA16816(acc, a, b0, b1)                                               \
    asm volatile("mma.sync.aligned.m16n8k16.row.col.f32.bf16.bf16.f32 "        \
                 "{%0,%1,%2,%3}, {%4,%5,%6,%7}, {%8,%9}, {%0,%1,%2,%3};"       \
                 : "+f"((acc)[0]), "+f"((acc)[1]), "+f"((acc)[2]), "+f"((acc)[3]) \
                 : "r"((a)[0]), "r"((a)[1]), "r"((a)[2]), "r"((a)[3]),         \
                   "r"(b0), "r"(b1))

// ---------------- init: zero bf16 h buffers (+ counters) ----------------
__global__ void k_init(int full) {
    int i = blockIdx.x * blockDim.x + threadIdx.x;
    uint4 z = make_uint4(0, 0, 0, 0);
    if (i < 16384) {
        ((uint4*)g_hh)[i] = z;
        ((uint4*)g_hl)[i] = z;
    }
    if (full && i < 4) g_cnt[i] = 0;
}

// ---------------- fused embedding gather + bf16 hi/lo split ----------------
__global__ void k_gatherSplit(const int* __restrict__ ids, const float* __restrict__ emb,
                              __nv_bfloat16* __restrict__ hi, __nv_bfloat16* __restrict__ lo) {
    int i = blockIdx.x * blockDim.x + threadIdx.x;   // float4 index over [B*T][512]
    int bt = i >> 7;
    int c  = i & 127;
    int id = __ldg(&ids[bt]);
    float4 v = __ldg((const float4*)emb + (size_t)id * 128 + c);
    __nv_bfloat16 h0 = __float2bfloat16(v.x), h1 = __float2bfloat16(v.y);
    __nv_bfloat16 h2 = __float2bfloat16(v.z), h3 = __float2bfloat16(v.w);
    __nv_bfloat16 l0 = __float2bfloat16(v.x - __bfloat162float(h0));
    __nv_bfloat16 l1 = __float2bfloat16(v.y - __bfloat162float(h1));
    __nv_bfloat16 l2 = __float2bfloat16(v.z - __bfloat162float(h2));
    __nv_bfloat16 l3 = __float2bfloat16(v.w - __bfloat162float(h3));
    ((__nv_bfloat162*)hi)[i*2]   = __nv_bfloat162(h0, h1);
    ((__nv_bfloat162*)hi)[i*2+1] = __nv_bfloat162(h2, h3);
    ((__nv_bfloat162*)lo)[i*2]   = __nv_bfloat162(l0, l1);
    ((__nv_bfloat162*)lo)[i*2+1] = __nv_bfloat162(l2, l3);
}

// ---------------- W split + transpose ----------------
__global__ void __launch_bounds__(256)
k_splitW(const float* __restrict__ W, __nv_bfloat16* __restrict__ hiT,
         __nv_bfloat16* __restrict__ loT, int K) {
    __shared__ float t[32][33];
    const int kb = blockIdx.y * 32, nb = blockIdx.x * 32;
    const int tx = threadIdx.x, ty = threadIdx.y;
#pragma unroll
    for (int r = ty; r < 32; r += 8)
        t[r][tx] = W[(size_t)(kb + r) * G4 + nb + tx];
    __syncthreads();
#pragma unroll
    for (int r = ty; r < 32; r += 8) {
        float v = t[tx][r];
        __nv_bfloat16 h = __float2bfloat16(v);
        __nv_bfloat16 l = __float2bfloat16(v - __bfloat162float(h));
        size_t o = (size_t)(nb + r) * K + kb + tx;
        hiT[o] = h;
        loT[o] = l;
    }
}

// ---------------- tensor-core projection GEMM (bf16 3-product split, double-buffered) ---
__global__ void __launch_bounds__(256)
k_hgemm(const __nv_bfloat16* __restrict__ Ahi, const __nv_bfloat16* __restrict__ Alo,
        const __nv_bfloat16* __restrict__ BhiT, const __nv_bfloat16* __restrict__ BloT,
        const float* __restrict__ bias, float* __restrict__ Y, int K) {
    const int N = 2048;
    __shared__ __nv_bfloat16 As[2][128 * 40];
    __shared__ __nv_bfloat16 Bs[2][128 * 40];

    const int tid = threadIdx.x;
    const int bm = blockIdx.y * 128, bn = blockIdx.x * 128;
    const int warp = tid >> 5, lane = tid & 31;
    const int mw = (warp & 1) * 64, nw = (warp >> 1) * 32;
    const int lr = lane >> 2, lc = (lane & 3) * 2;

    const int l_row = tid >> 2;
    const int l_q   = (tid & 3) * 8;

    float acc[4][4][4];
#pragma unroll
    for (int a = 0; a < 4; a++)
#pragma unroll
        for (int b = 0; b < 4; b++)
#pragma unroll
            for (int c = 0; c < 4; c++) acc[a][b][c] = 0.f;

    const int nk  = K >> 5;
    const int nch = 3 * nk;

    // preload chunk 0 -> regs -> smem buffer 0
    uint4 ra0 = *(const uint4*)(Ahi  + (size_t)(bm + l_row)      * K + l_q);
    uint4 ra1 = *(const uint4*)(Ahi  + (size_t)(bm + l_row + 64) * K + l_q);
    uint4 rb0 = *(const uint4*)(BhiT + (size_t)(bn + l_row)      * K + l_q);
    uint4 rb1 = *(const uint4*)(BhiT + (size_t)(bn + l_row + 64) * K + l_q);
    *(uint4*)&As[0][l_row * 40 + l_q]        = ra0;
    *(uint4*)&As[0][(l_row + 64) * 40 + l_q] = ra1;
    *(uint4*)&Bs[0][l_row * 40 + l_q]        = rb0;
    *(uint4*)&Bs[0][(l_row + 64) * 40 + l_q] = rb1;
    __syncthreads();

    for (int c = 0; c < nch; ++c) {
        const int cur = c & 1;
        // global loads for chunk c+1 (latency hidden by compute below)
        if (c + 1 < nch) {
            const int c1 = c + 1;
            const int seg = c1 / nk;
            const int k0 = (c1 - seg * nk) * 32;
            const __nv_bfloat16* Ap = (seg == 2) ? Alo  : Ahi;
            const __nv_bfloat16* Bp = (seg == 1) ? BloT : BhiT;
            ra0 = *(const uint4*)(Ap + (size_t)(bm + l_row)      * K + k0 + l_q);
            ra1 = *(const uint4*)(Ap + (size_t)(bm + l_row + 64) * K + k0 + l_q);
            rb0 = *(const uint4*)(Bp + (size_t)(bn + l_row)      * K + k0 + l_q);
            rb1 = *(const uint4*)(Bp + (size_t)(bn + l_row + 64) * K + k0 + l_q);
        }

#pragma unroll
        for (int kk = 0; kk < 32; kk += 16) {
            uint32_t af[4][4];
#pragma unroll
            for (int mf = 0; mf < 4; mf++) {
                const int r0 = (mw + mf * 16 + lr) * 40 + kk + lc;
                af[mf][0] = *(const uint32_t*)&As[cur][r0];
                af[mf][1] = *(const uint32_t*)&As[cur][r0 + 8 * 40];
                af[mf][2] = *(const uint32_t*)&As[cur][r0 + 8];
                af[mf][3] = *(const uint32_t*)&As[cur][r0 + 8 * 40 + 8];
            }
            uint32_t bfr[4][2];
#pragma unroll
            for (int nf = 0; nf < 4; nf++) {
                const int rb = (nw + nf * 8 + lr) * 40 + kk + lc;
                bfr[nf][0] = *(const uint32_t*)&Bs[cur][rb];
                bfr[nf][1] = *(const uint32_t*)&Bs[cur][rb + 8];
            }
#pragma unroll
            for (int mf = 0; mf < 4; mf++)
#pragma unroll
                for (int nf = 0; nf < 4; nf++)
                    MMA16816(acc[mf][nf], af[mf], bfr[nf][0], bfr[nf][1]);
        }

        // store chunk c+1 into the other buffer (overlaps with mma above)
        if (c + 1 < nch) {
            const int nxt = cur ^ 1;
            *(uint4*)&As[nxt][l_row * 40 + l_q]        = ra0;
            *(uint4*)&As[nxt][(l_row + 64) * 40 + l_q] = ra1;
            *(uint4*)&Bs[nxt][l_row * 40 + l_q]        = rb0;
            *(uint4*)&Bs[nxt][(l_row + 64) * 40 + l_q] = rb1;
        }
        __syncthreads();
    }

#pragma unroll
    for (int nf = 0; nf < 4; nf++) {
        const int col = bn + nw + nf * 8 + lc;
        const float bz0 = __ldg(&bias[col]), bz1 = __ldg(&bias[col + 1]);
#pragma unroll
        for (int mf = 0; mf < 4; mf++) {
            const int row0 = bm + mw + mf * 16 + lr;
            float2 v0, v1;
            v0.x = acc[mf][nf][0] + bz0; v0.y = acc[mf][nf][1] + bz1;
            v1.x = acc[mf][nf][2] + bz0; v1.y = acc[mf][nf][3] + bz1;
            *(float2*)&Y[(size_t)row0 * N + col]       = v0;
            *(float2*)&Y[(size_t)(row0 + 8) * N + col] = v1;
        }
    }
}

// ---------------- persistent bidirectional LSTM recurrence (tensor-core) ----------------
// R7 winner + (a) outputs moved into barrier shadow (fence drains only the 2
// h-state stores), (b) 4 HMMA accumulator chains per warp, (c) layer 1 writes
// its bf16 hi/lo split directly (oh/ol) instead of fp32 hs_out.
__global__ void __launch_bounds__(REC_THREADS, 1)
k_rec(const float* __restrict__ xzf, const float* __restrict__ xzb,
      const float* __restrict__ Uf,  const float* __restrict__ Ub,
      float* __restrict__ hs_out, float* st_out,
      __nv_bfloat16* __restrict__ oh, __nv_bfloat16* __restrict__ ol, int layer) {
    extern __shared__ __nv_bfloat16 smb[];
    __nv_bfloat16* Ahi = smb;                  // [64][AROW]
    __nv_bfloat16* Alo = Ahi + 64 * AROW;      // [64][AROW]
    __nv_bfloat16* Uhi = Alo + 64 * AROW;      // [32][AROW]
    __nv_bfloat16* Ulo = Uhi + 32 * AROW;      // [32][AROW]
    float* zf = (float*)(Ulo + 32 * AROW);     // [64][ZST]

    const int dir = blockIdx.x >> 6;
    const int cid = blockIdx.x & 63;
    const float* xz = dir ? xzb : xzf;
    const float* U  = dir ? Ub  : Uf;
    int* cnt = &g_cnt[layer * 2 + dir];
    const int jbase = cid * 8;
    const int tid = threadIdx.x;
    const int lane = tid & 31, warp = tid >> 5;

    for (int idx = tid; idx < 512 * 32; idx += REC_THREADS) {
        int k = idx >> 5, n = idx & 31;
        float v = U[(size_t)k * G4 + (n >> 3) * Hh + jbase + (n & 7)];
        __nv_bfloat16 h = __float2bfloat16(v);
        Uhi[n * AROW + k] = h;
        Ulo[n * AROW + k] = __float2bfloat16(v - __bfloat162float(h));
    }

    const int eb = tid >> 2;
    const int eu = (tid & 3) * 2;
    float c0 = 0.f, c1 = 0.f;

    const int sr = tid >> 2, sq = tid & 3;

    const int mf  = warp & 3;
    const int nfg = warp >> 2;
    const int nb0 = nfg * 16;
    const uint32_t aoff  = (uint32_t)(((mf * 16 + (lane & 15)) * AROW + ((lane >> 4) << 3)) * 2);
    const uint32_t boff0 = (uint32_t)(((nb0 + (lane & 7)) * AROW + ((lane >> 3) << 3)) * 2);
    const uint32_t boff1 = boff0 + (uint32_t)(8 * AROW * 2);
    const uint32_t sAhi = (uint32_t)__cvta_generic_to_shared(Ahi);
    const uint32_t sAlo = (uint32_t)__cvta_generic_to_shared(Alo);
    const uint32_t sUhi = (uint32_t)__cvta_generic_to_shared(Uhi);
    const uint32_t sUlo = (uint32_t)__cvta_generic_to_shared(Ulo);

    const __nv_bfloat16* HHb = g_hh + (size_t)dir * 2 * Bsz * Hh;
    const __nv_bfloat16* HLb = g_hl + (size_t)dir * 2 * Bsz * Hh;

    __syncthreads();

    for (int s = 0; s < Tt; ++s) {
        const int tt = dir ? (Tt - 1 - s) : s;
        const int par = s & 1;
        const __nv_bfloat16* hpH = HHb + par * Bsz * Hh;
        const __nv_bfloat16* hpL = HLb + par * Bsz * Hh;
        __nv_bfloat16* hnH = (__nv_bfloat16*)HHb + (par ^ 1) * Bsz * Hh;
        __nv_bfloat16* hnL = (__nv_bfloat16*)HLb + (par ^ 1) * Bsz * Hh;

        // prefetch xz gate pre-activations
        const float* xzp = xz + ((size_t)eb * Tt + tt) * G4 + jbase;
        float x[8];
#pragma unroll
        for (int g = 0; g < 4; ++g) {
            x[g * 2]     = __ldcs(xzp + g * 512 + eu);
            x[g * 2 + 1] = __ldcs(xzp + g * 512 + eu + 1);
        }

        // stage h hi (group 0), then h lo (group 1)
        {
            const uint4* srcH = (const uint4*)(hpH + sr * 512);
            const uint4* srcL = (const uint4*)(hpL + sr * 512);
            const uint32_t dH = sAhi + (uint32_t)(sr * AROW * 2) + sq * 16;
            const uint32_t dL = sAlo + (uint32_t)(sr * AROW * 2) + sq * 16;
#pragma unroll
            for (int i = 0; i < 16; ++i) cpasync16(dH + i * 64, srcH + sq + 4 * i);
            asm volatile("cp.async.commit_group;");
#pragma unroll
            for (int i = 0; i < 16; ++i) cpasync16(dL + i * 64, srcL + sq + 4 * i);
            asm volatile("cp.async.commit_group;");
        }

        float a0c0[4] = {0.f,0.f,0.f,0.f}, a0c1[4] = {0.f,0.f,0.f,0.f};
        float a1c0[4] = {0.f,0.f,0.f,0.f}, a1c1[4] = {0.f,0.f,0.f,0.f};

        // ---- wait hi group; run Ahi@Uhi and Ahi@Ulo while lo group flies ----
        asm volatile("cp.async.wait_group 1;" ::: "memory");
        __syncthreads();
#pragma unroll
        for (int p = 0; p < 2; ++p) {
            const uint32_t ab  = sAhi + aoff;
            const uint32_t bb0 = (p == 1 ? sUlo : sUhi) + boff0;
            const uint32_t bb1 = (p == 1 ? sUlo : sUhi) + boff1;
#pragma unroll 4
            for (int kb = 0; kb < 16; ++kb) {
                const uint32_t ko = kb * 64;
                uint32_t a0[4], a1[4], b0[4], b1[4];
                LDSM4(a0, ab + ko);
                LDSM4(a1, ab + ko + 32);
                LDSM4(b0, bb0 + ko);
                LDSM4(b1, bb1 + ko);
                MMA16816(a0c0, a0, b0[0], b0[1]);
                MMA16816(a0c1, a0, b1[0], b1[1]);
                MMA16816(a1c0, a1, b0[2], b0[3]);
                MMA16816(a1c1, a1, b1[2], b1[3]);
            }
        }
        // ---- wait lo group; run Alo@Uhi ----
        asm volatile("cp.async.wait_group 0;" ::: "memory");
        __syncthreads();
        {
            const uint32_t ab  = sAlo + aoff;
            const uint32_t bb0 = sUhi + boff0;
            const uint32_t bb1 = sUhi + boff1;
#pragma unroll 4
            for (int kb = 0; kb < 16; ++kb) {
                const uint32_t ko = kb * 64;
                uint32_t a0[4], a1[4], b0[4], b1[4];
                LDSM4(a0, ab + ko);
                LDSM4(a1, ab + ko + 32);
                LDSM4(b0, bb0 + ko);
                LDSM4(b1, bb1 + ko);
                MMA16816(a0c0, a0, b0[0], b0[1]);
                MMA16816(a0c1, a0, b1[0], b1[1]);
                MMA16816(a1c0, a1, b0[2], b0[3]);
                MMA16816(a1c1, a1, b1[2], b1[3]);
            }
        }

        // write z tiles to SMEM (combine the split accumulator chains)
        {
            const int lr = lane >> 2, lc = (lane & 3) * 2;
            const int zr = mf * 16 + lr;
            *(float2*)&zf[zr * ZST + nb0 + lc] =
                make_float2(a0c0[0] + a1c0[0], a0c0[1] + a1c0[1]);
            *(float2*)&zf[(zr + 8) * ZST + nb0 + lc] =
                make_float2(a0c0[2] + a1c0[2], a0c0[3] + a1c0[3]);
            *(float2*)&zf[zr * ZST + nb0 + 8 + lc] =
                make_float2(a0c1[0] + a1c1[0], a0c1[1] + a1c1[1]);
            *(float2*)&zf[(zr + 8) * ZST + nb0 + 8 + lc] =
                make_float2(a0c1[2] + a1c1[2], a0c1[3] + a1c1[3]);
        }
        __syncthreads();

        // epilogue: 2 hidden units per thread; write ONLY h-state before the fence
        float hv[2];
        __nv_bfloat16 hb[2], lb[2];
#pragma unroll
        for (int e = 0; e < 2; ++e) {
            const int u = eu + e;
            const float zi = zf[eb * ZST + u]      + x[0 + e];
            const float zF = zf[eb * ZST + 8 + u]  + x[2 + e];
            const float zg = zf[eb * ZST + 16 + u] + x[4 + e];
            const float zo = zf[eb * ZST + 24 + u] + x[6 + e];
            const float ig = sigm(zi), fg = sigm(zF);
            const float gg = tanhf(zg), og = sigm(zo);
            float& c = e ? c1 : c0;
            c = fg * c + ig * gg;
            hv[e] = og * tanhf(c);
            hb[e] = __float2bfloat16(hv[e]);
            lb[e] = __float2bfloat16(hv[e] - __bfloat162float(hb[e]));
            hnH[eb * Hh + jbase + u] = hb[e];
            hnL[eb * Hh + jbase + u] = lb[e];
        }

        // fence (drains only the 4 small h-state stores) + arrive
        __threadfence();
        __syncthreads();
        if (tid == 0) atomicAdd(cnt, 1);

        // bulk output stores in the barrier shadow
        const size_t ob = ((size_t)eb * Tt + tt) * 1024 + dir * Hh + jbase + eu;
        if (hs_out != nullptr) {
            hs_out[ob]     = hv[0];
            hs_out[ob + 1] = hv[1];
            if (st_out != nullptr && s == Tt - 1) {
#pragma unroll
                for (int e = 0; e < 2; ++e) {
                    st_out[eb * 1024 + dir * Hh + jbase + eu + e] = hv[e];
                    st_out[Bsz * 1024 + eb * 1024 + dir * Hh + jbase + eu + e] = e ? c1 : c0;
                }
            }
        } else {
            oh[ob] = hb[0]; oh[ob + 1] = hb[1];
            ol[ob] = lb[0]; ol[ob + 1] = lb[1];
        }

        // spin for all CTAs of this direction
        if (tid == 0) {
            const int target = NC * (s + 1);
            int v;
            do {
                asm volatile("ld.acquire.gpu.global.s32 %0, [%1];"
                             : "=r"(v) : "l"(cnt) : "memory");
            } while (v < target);
        }
        __syncthreads();
    }
}

// ---------------- launch sequence ----------------
extern "C" void kernel_launch(void* const* d_in, const int* in_sizes, int n_in,
                              void* d_out, int out_size) {
    const int*   ids = (const int*)d_in[0];
    const float* emb = (const float*)d_in[1];
    const float *W1f = (const float*)d_in[2],  *U1f = (const float*)d_in[3],
                *b1f = (const float*)d_in[4];
    const float *W1b = (const float*)d_in[5],  *U1b = (const float*)d_in[6],
                *b1b = (const float*)d_in[7];
    const float *W2f = (const float*)d_in[8],  *U2f = (const float*)d_in[9],
                *b2f = (const float*)d_in[10];
    const float *W2b = (const float*)d_in[11], *U2b = (const float*)d_in[12],
                *b2b = (const float*)d_in[13];
    float* out = (float*)d_out;

    float *pxz0, *pxz1;
    __nv_bfloat16 *pahi, *palo, *pwhi, *pwlo;
    cudaGetSymbolAddress((void**)&pxz0, g_xz0);
    cudaGetSymbolAddress((void**)&pxz1, g_xz1);
    cudaGetSymbolAddress((void**)&pahi, g_ahi);
    cudaGetSymbolAddress((void**)&palo, g_alo);
    cudaGetSymbolAddress((void**)&pwhi, g_whiT);
    cudaGetSymbolAddress((void**)&pwlo, g_wloT);

    cudaFuncSetAttribute(k_rec, cudaFuncAttributeMaxDynamicSharedMemorySize, REC_SMEM);

    k_init<<<128, 256>>>(1);
    // fused gather + layer-1 A split (A layout [B*T][512] hi/lo)
    k_gatherSplit<<<16384, 256>>>(ids, emb, pahi, palo);

    const dim3 gg(G4 / 128, (Bsz * Tt) / 128);   // (16, 256)
    const dim3 tw(32, 8);

    // ----- layer 1 (K = 512) -----
    {
        const int K = Ee;
        k_splitW<<<dim3(G4 / 32, K / 32), tw>>>(W1f, pwhi, pwlo, K);
        k_hgemm<<<gg, 256>>>(pahi, palo, pwhi, pwlo, b1f, pxz0, K);
        k_splitW<<<dim3(G4 / 32, K / 32), tw>>>(W1b, pwhi, pwlo, K);
        k_hgemm<<<gg, 256>>>(pahi, palo, pwhi, pwlo, b1b, pxz1, K);
    }
    // layer-1 recurrence writes its output directly as bf16 hi/lo (layer-2 A)
    k_rec<<<2 * NC, REC_THREADS, REC_SMEM>>>(pxz0, pxz1, U1f, U1b,
                                             nullptr, nullptr, pahi, palo, 0);
    k_init<<<128, 256>>>(0);

    // ----- layer 2 (K = 1024) -----
    {
        const int K = 2 * Hh;
        k_splitW<<<dim3(G4 / 32, K / 32), tw>>>(W2f, pwhi, pwlo, K);
        k_hgemm<<<gg, 256>>>(pahi, palo, pwhi, pwlo, b2f, pxz0, K);
        k_splitW<<<dim3(G4 / 32, K / 32), tw>>>(W2b, pwhi, pwlo, K);
        k_hgemm<<<gg, 256>>>(pahi, palo, pwhi, pwlo, b2b, pxz1, K);
    }
    k_rec<<<2 * NC, REC_THREADS, REC_SMEM>>>(pxz0, pxz1, U2f, U2b, out,
                                             out + (size_t)Bsz * Tt * 1024,
                                             nullptr, nullptr, 1);
}